// round 10
// baseline (speedup 1.0000x reference)
#include <cuda_runtime.h>
#include <cuda_bf16.h>
#include <stdint.h>

#define B_   8
#define N_   1024
#define C_   1024
#define HD_  64
#define FF_  4096
#define BH_  128
#define M_   8192
#define KSP  102

typedef __nv_bfloat16 bf16;
typedef __nv_bfloat162 bf162;

// ---------------- scratch ----------------
__device__ __align__(256) float g_v[(size_t)BH_*N_*HD_];
__device__ __align__(256) float g_x1[(size_t)M_*C_];
__device__ __align__(256) bf16 g_qh[(size_t)BH_*N_*HD_], g_ql[(size_t)BH_*N_*HD_];
__device__ __align__(256) bf16 g_kh[(size_t)BH_*N_*HD_], g_kl[(size_t)BH_*N_*HD_];
__device__ __align__(256) bf16 g_xnh[(size_t)M_*C_],  g_xnl[(size_t)M_*C_];
__device__ __align__(256) bf16 g_hnh[(size_t)M_*C_],  g_hnl[(size_t)M_*C_];
__device__ __align__(256) bf16 g_ath[(size_t)M_*C_],  g_atl[(size_t)M_*C_];
__device__ __align__(256) bf16 g_h1h[(size_t)M_*FF_], g_h1l[(size_t)M_*FF_];
__device__ __align__(256) bf16 g_qwh[(size_t)3*C_*C_], g_qwl[(size_t)3*C_*C_];
__device__ __align__(256) bf16 g_owh[(size_t)C_*C_],   g_owl[(size_t)C_*C_];
__device__ __align__(256) bf16 g_w1h[(size_t)FF_*C_],  g_w1l[(size_t)FF_*C_];
__device__ __align__(256) bf16 g_w2h[(size_t)C_*FF_],  g_w2l[(size_t)C_*FF_];

// ---------------- helpers ----------------
__device__ __forceinline__ uint32_t s2u(const void* p) {
    uint32_t a;
    asm("{ .reg .u64 t; cvta.to.shared.u64 t, %1; cvt.u32.u64 %0, t; }" : "=r"(a) : "l"(p));
    return a;
}
__device__ __forceinline__ void bfsplit(float v, bf16& h, bf16& l) {
    h = __float2bfloat16(v);
    l = __float2bfloat16(v - __bfloat162float(h));
}
__device__ __forceinline__ void ldsm4(uint32_t* r, uint32_t a) {
    asm volatile("ldmatrix.sync.aligned.m8n8.x4.shared.b16 {%0,%1,%2,%3}, [%4];"
        : "=r"(r[0]), "=r"(r[1]), "=r"(r[2]), "=r"(r[3]) : "r"(a));
}
__device__ __forceinline__ void mma16816(float* c, const uint32_t* a, const uint32_t* b) {
    asm volatile("mma.sync.aligned.m16n8k16.row.col.f32.bf16.bf16.f32 "
        "{%0,%1,%2,%3}, {%4,%5,%6,%7}, {%8,%9}, {%0,%1,%2,%3};"
        : "+f"(c[0]), "+f"(c[1]), "+f"(c[2]), "+f"(c[3])
        : "r"(a[0]), "r"(a[1]), "r"(a[2]), "r"(a[3]), "r"(b[0]), "r"(b[1]));
}
#define CP_ASYNC16(s, g) \
    asm volatile("cp.async.cg.shared.global [%0], [%1], 16;" :: "r"(s), "l"(g))
#define CP_COMMIT() asm volatile("cp.async.commit_group;" ::: "memory")
#define CP_WAIT0()  asm volatile("cp.async.wait_group 0;" ::: "memory")

// ---------------- weight split: ALL four weights in ONE launch ------------
__global__ void __launch_bounds__(256)
cvt4(const float* __restrict__ s0, bf16* __restrict__ h0, bf16* __restrict__ l0, int n0,
     const float* __restrict__ s1, bf16* __restrict__ h1, bf16* __restrict__ l1, int n1,
     const float* __restrict__ s2, bf16* __restrict__ h2, bf16* __restrict__ l2, int n2,
     const float* __restrict__ s3, bf16* __restrict__ h3, bf16* __restrict__ l3, int n3)
{
    int i = blockIdx.x * 256 + threadIdx.x;
    const float* s; bf16 *h, *l;
    if (i < n0) { s = s0; h = h0; l = l0; }
    else if ((i -= n0) < n1) { s = s1; h = h1; l = l1; }
    else if ((i -= n1) < n2) { s = s2; h = h2; l = l2; }
    else { i -= n2; if (i >= n3) return; s = s3; h = h3; l = l3; }
    float4 v = ((const float4*)s)[i];
    bf16 a0,a1,a2,a3,b0,b1,b2,b3;
    bfsplit(v.x,a0,b0); bfsplit(v.y,a1,b1); bfsplit(v.z,a2,b2); bfsplit(v.w,a3,b3);
    bf162 p,q;
    p.x=a0;p.y=a1;q.x=a2;q.y=a3; ((bf162*)h)[i*2]=p; ((bf162*)h)[i*2+1]=q;
    p.x=b0;p.y=b1;q.x=b2;q.y=b3; ((bf162*)l)[i*2]=p; ((bf162*)l)[i*2+1]=q;
}

// ---------------- LayerNorm -> bf16 hi/lo ----------------
__global__ void __launch_bounds__(256)
ln_bf16(const float* __restrict__ x, const float* __restrict__ w,
        const float* __restrict__ b, bf16* __restrict__ yh, bf16* __restrict__ yl)
{
    __shared__ float red[16];
    int row = blockIdx.x, t = threadIdx.x;
    float4 v = ((const float4*)(x + (size_t)row * 1024))[t];
    float s  = v.x + v.y + v.z + v.w;
    float ss = v.x*v.x + v.y*v.y + v.z*v.z + v.w*v.w;
    #pragma unroll
    for (int o = 16; o; o >>= 1) {
        s  += __shfl_xor_sync(~0u, s, o);
        ss += __shfl_xor_sync(~0u, ss, o);
    }
    if ((t & 31) == 0) { red[t>>5] = s; red[(t>>5)+8] = ss; }
    __syncthreads();
    if (t == 0) {
        float ts=0.f, tss=0.f;
        #pragma unroll
        for (int i = 0; i < 8; ++i) { ts += red[i]; tss += red[i+8]; }
        float mu = ts * (1.f/1024.f);
        red[0] = mu; red[1] = rsqrtf(tss*(1.f/1024.f) - mu*mu + 1e-5f);
    }
    __syncthreads();
    float mu = red[0], rs = red[1];
    float4 wv = ((const float4*)w)[t];
    float4 bv = ((const float4*)b)[t];
    float o0 = (v.x-mu)*rs*wv.x + bv.x, o1 = (v.y-mu)*rs*wv.y + bv.y;
    float o2 = (v.z-mu)*rs*wv.z + bv.z, o3 = (v.w-mu)*rs*wv.w + bv.w;
    bf16 h0,h1,h2,h3,l0,l1,l2,l3;
    bfsplit(o0,h0,l0); bfsplit(o1,h1,l1); bfsplit(o2,h2,l2); bfsplit(o3,h3,l3);
    size_t oi = ((size_t)row*1024 + t*4) >> 1;
    bf162 pa, pb;
    pa.x=h0;pa.y=h1;pb.x=h2;pb.y=h3; ((bf162*)yh)[oi]=pa; ((bf162*)yh)[oi+1]=pb;
    pa.x=l0;pa.y=l1;pb.x=l2;pb.y=l3; ((bf162*)yl)[oi]=pa; ((bf162*)yl)[oi+1]=pb;
}

// ---- HMMA GEMM: 128x128 tile, 256 thr, 2-stage, 2 CTAs/SM, bf16x3 ----
#define ATILE_B  10240
#define STAGE_B  40960
#define GSMEM    (2*STAGE_B)

__device__ __forceinline__ void issue_stage(
    const bf16* __restrict__ Ah, const bf16* __restrict__ Al,
    const bf16* __restrict__ Bh, const bf16* __restrict__ Bl,
    uint32_t sbase, int bm, int bn, int ko, int K, int tid)
{
    #pragma unroll
    for (int i = 0; i < 8; ++i) {
        int lin = tid + (i << 8);
        int tile = lin >> 9;
        int wit = lin & 511;
        int r = wit >> 2, ch = wit & 3;
        const bf16* gp;
        if      (tile == 0) gp = Ah + (size_t)(bm + r) * K + ko + ch*8;
        else if (tile == 1) gp = Al + (size_t)(bm + r) * K + ko + ch*8;
        else if (tile == 2) gp = Bh + (size_t)(bn + r) * K + ko + ch*8;
        else                gp = Bl + (size_t)(bn + r) * K + ko + ch*8;
        CP_ASYNC16(sbase + tile*ATILE_B + r*80 + ch*16, gp);
    }
    CP_COMMIT();
}

template<int EPI>
__global__ void __launch_bounds__(256, 2)
tc_gemm(const bf16* __restrict__ Ah, const bf16* __restrict__ Al,
        const bf16* __restrict__ Bh, const bf16* __restrict__ Bl,
        const float* __restrict__ bias, const float* __restrict__ aux,
        const float* __restrict__ res, float* __restrict__ outf,
        bf16* __restrict__ outh, bf16* __restrict__ outl, int N, int K)
{
    extern __shared__ char smem[];
    uint32_t sb = s2u(smem);
    const int tid = threadIdx.x, lane = tid & 31, wid = tid >> 5;
    const int wm = wid & 3, wn = wid >> 2;
    const int bm = blockIdx.y << 7, bn = blockIdx.x << 7;

    float acc[2][8][4];
    #pragma unroll
    for (int i = 0; i < 2; ++i)
        #pragma unroll
        for (int j = 0; j < 8; ++j)
            #pragma unroll
            for (int q = 0; q < 4; ++q) acc[i][j][q] = 0.f;

    const int ktn = K >> 5;
    issue_stage(Ah, Al, Bh, Bl, sb, bm, bn, 0, K, tid);

    const int a_ro = (lane & 15);
    const int a_ko = (lane >> 4) * 8;
    const int b_rp = ((lane >> 4) & 1) * 8 + (lane & 7);
    const int b_ko = ((lane >> 3) & 1) * 8;

    for (int kt = 0; kt < ktn; ++kt) {
        CP_WAIT0();
        __syncthreads();
        if (kt + 1 < ktn)
            issue_stage(Ah, Al, Bh, Bl, sb + ((kt + 1) & 1) * STAGE_B,
                        bm, bn, (kt + 1) * 32, K, tid);
        uint32_t st = sb + (kt & 1) * STAGE_B;
        #pragma unroll
        for (int ks = 0; ks < 2; ++ks) {
            uint32_t ahi[2][4], alo[2][4], bhi[4][4], blo[4][4];
            #pragma unroll
            for (int mf = 0; mf < 2; ++mf)
                ldsm4(ahi[mf], st + (wm*32 + mf*16 + a_ro)*80 + (ks*16 + a_ko)*2);
            #pragma unroll
            for (int np = 0; np < 4; ++np)
                ldsm4(bhi[np], st + 2*ATILE_B + (wn*64 + np*16 + b_rp)*80 + (ks*16 + b_ko)*2);
            #pragma unroll
            for (int np = 0; np < 4; ++np)
                #pragma unroll
                for (int mf = 0; mf < 2; ++mf) {
                    mma16816(acc[mf][np*2  ], ahi[mf], &bhi[np][0]);
                    mma16816(acc[mf][np*2+1], ahi[mf], &bhi[np][2]);
                }
            #pragma unroll
            for (int np = 0; np < 4; ++np)
                ldsm4(blo[np], st + 2*ATILE_B + ATILE_B + (wn*64 + np*16 + b_rp)*80 + (ks*16 + b_ko)*2);
            #pragma unroll
            for (int np = 0; np < 4; ++np)
                #pragma unroll
                for (int mf = 0; mf < 2; ++mf) {
                    mma16816(acc[mf][np*2  ], ahi[mf], &blo[np][0]);
                    mma16816(acc[mf][np*2+1], ahi[mf], &blo[np][2]);
                }
            #pragma unroll
            for (int mf = 0; mf < 2; ++mf)
                ldsm4(alo[mf], st + ATILE_B + (wm*32 + mf*16 + a_ro)*80 + (ks*16 + a_ko)*2);
            #pragma unroll
            for (int np = 0; np < 4; ++np)
                #pragma unroll
                for (int mf = 0; mf < 2; ++mf) {
                    mma16816(acc[mf][np*2  ], alo[mf], &bhi[np][0]);
                    mma16816(acc[mf][np*2+1], alo[mf], &bhi[np][2]);
                }
        }
    }

    const int tr = lane >> 2;
    const int tc = (lane & 3) * 2;
    #pragma unroll
    for (int mf = 0; mf < 2; ++mf) {
        #pragma unroll
        for (int nf = 0; nf < 8; ++nf) {
            int gj = bn + wn*64 + nf*8 + tc;
            float2 b2 = *(const float2*)&bias[gj];
            #pragma unroll
            for (int h = 0; h < 2; ++h) {
                int gi = bm + wm*32 + mf*16 + tr + h*8;
                float v0 = acc[mf][nf][h*2]   + b2.x;
                float v1 = acc[mf][nf][h*2+1] + b2.y;
                size_t off = (size_t)gi * N + gj;
                if (EPI == 0) {
                    int wh = gj >> 10, hh = (gj >> 6) & 15, d = gj & 63;
                    int bb = gi >> 10, nn = gi & 1023;
                    size_t idx = (((size_t)(bb*16 + hh))*1024 + nn)*64 + d;
                    if (wh == 2) {
                        float2 o; o.x = v0; o.y = v1;
                        *(float2*)&g_v[idx] = o;
                    } else {
                        bf16 h0,l0,h1,l1;
                        bfsplit(v0,h0,l0); bfsplit(v1,h1,l1);
                        bf162 ph, pl; ph.x=h0; ph.y=h1; pl.x=l0; pl.y=l1;
                        if (wh == 0) { *(bf162*)&g_qh[idx]=ph; *(bf162*)&g_ql[idx]=pl; }
                        else         { *(bf162*)&g_kh[idx]=ph; *(bf162*)&g_kl[idx]=pl; }
                    }
                } else if (EPI == 1) {
                    float2 rr = *(const float2*)&res[off];
                    float2 o; o.x = v0 + rr.x; o.y = v1 + rr.y;
                    *(float2*)&outf[off] = o;
                } else if (EPI == 2) {
                    float2 m = *(const float2*)&aux[off];
                    v0 = (m.x > 0.5f) ? fmaxf(v0, 0.f) : 0.f;
                    v1 = (m.y > 0.5f) ? fmaxf(v1, 0.f) : 0.f;
                    bf16 h0,l0,h1,l1;
                    bfsplit(v0,h0,l0); bfsplit(v1,h1,l1);
                    bf162 p; p.x=h0; p.y=h1; *(bf162*)&outh[off] = p;
                    p.x=l0; p.y=l1;          *(bf162*)&outl[off] = p;
                } else {
                    float2 m  = *(const float2*)&aux[off];
                    float2 rr = *(const float2*)&res[off];
                    float2 o;
                    o.x = rr.x + ((m.x > 0.5f) ? v0 : 0.f);
                    o.y = rr.y + ((m.y > 0.5f) ? v1 : 0.f);
                    *(float2*)&outf[off] = o;
                }
            }
        }
    }
}

// ------- sparse attention: HMMA scores, joint 2-row topk + sparse PV -------
#define SS_STR  1034
#define SS_OFF  20736
#define ATTN_SMEM (9216 + 73728 + 32*SS_STR*4)

__device__ __forceinline__ void issue_k(uint32_t sb, size_t bhoff, int kt, int buf, int tid) {
    #pragma unroll
    for (int i = 0; i < 4; ++i) {
        int lin = tid + (i << 9);
        int tile = lin >> 10, wit = lin & 1023;
        int r = wit >> 3, ch = wit & 7;
        const bf16* gsrc = (tile ? g_kl : g_kh) + bhoff + (size_t)(kt*128 + r)*64 + ch*8;
        CP_ASYNC16(sb + 9216 + buf*36864 + tile*18432 + r*144 + ch*16, gsrc);
    }
    CP_COMMIT();
}

__device__ __forceinline__ float dec(unsigned ub) {
    unsigned fb = ub ^ ((ub & 0x80000000u) ? 0x80000000u : 0xFFFFFFFFu);
    return __uint_as_float(fb);
}

__global__ void __launch_bounds__(512)
attn_kernel()
{
    extern __shared__ char smraw[];
    float* smf = (float*)smraw;
    uint32_t sb = s2u(smraw);

    int blk = blockIdx.x, bh = blk >> 5, n0 = (blk & 31) << 5;
    int tid = threadIdx.x, lane = tid & 31, w = tid >> 5;
    const size_t bhoff = (size_t)bh * 65536;

    {
        int tile = tid >> 8, wit = tid & 255, r = wit >> 3, ch = wit & 7;
        const bf16* gsrc = (tile ? g_ql : g_qh) + bhoff + (size_t)(n0 + r)*64 + ch*8;
        *(uint4*)(smraw + tile*4608 + r*144 + ch*16) = *(const uint4*)gsrc;
    }
    issue_k(sb, bhoff, 0, 0, tid);
    __syncthreads();

    const int wm = w & 1, wn = w >> 1;
    const int a_ro = lane & 15, a_ko = (lane >> 4) * 8;
    const int b_rp = ((lane >> 4) & 1) * 8 + (lane & 7);
    const int b_ko = ((lane >> 3) & 1) * 8;
    uint32_t qhi[4][4], qlo[4][4];
    #pragma unroll
    for (int ks = 0; ks < 4; ++ks) {
        uint32_t qa = sb + (wm*16 + a_ro)*144 + (ks*16 + a_ko)*2;
        ldsm4(qhi[ks], qa);
        ldsm4(qlo[ks], qa + 4608);
    }
    const int tr = lane >> 2, tc = (lane & 3) * 2;

    // ---- phase 1: scores via HMMA (double-buffered K) ----
    for (int kt = 0; kt < 8; ++kt) {
        CP_WAIT0();
        __syncthreads();
        if (kt < 7) issue_k(sb, bhoff, kt + 1, (kt + 1) & 1, tid);
        uint32_t kb = sb + 9216 + (kt & 1)*36864;
        float acc[2][4];
        #pragma unroll
        for (int nf = 0; nf < 2; ++nf)
            #pragma unroll
            for (int q = 0; q < 4; ++q) acc[nf][q] = 0.f;
        #pragma unroll
        for (int ks = 0; ks < 4; ++ks) {
            uint32_t bd = kb + (wn*16 + b_rp)*144 + (ks*16 + b_ko)*2;
            uint32_t bhi[4], blo[4];
            ldsm4(bhi, bd);
            ldsm4(blo, bd + 18432);
            mma16816(acc[0], qhi[ks], &bhi[0]);
            mma16816(acc[1], qhi[ks], &bhi[2]);
            mma16816(acc[0], qhi[ks], &blo[0]);
            mma16816(acc[1], qhi[ks], &blo[2]);
            mma16816(acc[0], qlo[ks], &bhi[0]);
            mma16816(acc[1], qlo[ks], &bhi[2]);
        }
        #pragma unroll
        for (int nf = 0; nf < 2; ++nf) {
            int key = kt*128 + wn*16 + nf*8 + tc;
            int row0 = wm*16 + tr;
            float2 o;
            o.x = acc[nf][0]*0.125f; o.y = acc[nf][1]*0.125f;
            *(float2*)&smf[SS_OFF + row0*SS_STR + key] = o;
            o.x = acc[nf][2]*0.125f; o.y = acc[nf][3]*0.125f;
            *(float2*)&smf[SS_OFF + (row0+8)*SS_STR + key] = o;
        }
    }
    __syncthreads();

    // ---- joint 2-row: topk threshold, softmax, compaction, sparse PV ----
    int r0 = 2 * w;
    float* srow0 = &smf[SS_OFF + r0 * SS_STR];
    float* srow1 = srow0 + SS_STR;
    const float* Vb = g_v + bhoff;

    unsigned key0[32], key1[32];
    float lmax0 = -3.4e38f, lmax1 = -3.4e38f;
    #pragma unroll
    for (int i = 0; i < 32; ++i) {
        float s0 = srow0[lane + 32*i];
        float s1 = srow1[lane + 32*i];
        lmax0 = fmaxf(lmax0, s0);
        lmax1 = fmaxf(lmax1, s1);
        unsigned u0 = __float_as_uint(s0), u1 = __float_as_uint(s1);
        key0[i] = u0 ^ (((unsigned)((int)u0 >> 31)) | 0x80000000u);
        key1[i] = u1 ^ (((unsigned)((int)u1 >> 31)) | 0x80000000u);
    }
    #pragma unroll
    for (int o = 16; o; o >>= 1) {
        lmax0 = fmaxf(lmax0, __shfl_xor_sync(~0u, lmax0, o));
        lmax1 = fmaxf(lmax1, __shfl_xor_sync(~0u, lmax1, o));
    }

    // joint binary search: both rows' counts packed into one reduce
    unsigned lo0 = 0u, hi0 = 0xFFFFFFFFu, lo1 = 0u, hi1 = 0xFFFFFFFFu;
    bool d0 = false, d1 = false;
    while (!d0 || !d1) {
        unsigned mid0 = d0 ? lo0 : (lo0 + (unsigned)(((unsigned long long)(hi0 - lo0) + 1ull) >> 1));
        unsigned mid1 = d1 ? lo1 : (lo1 + (unsigned)(((unsigned long long)(hi1 - lo1) + 1ull) >> 1));
        unsigned c = 0;
        #pragma unroll
        for (int i = 0; i < 32; ++i) {
            c += (key0[i] >= mid0) ? 1u : 0u;
            c += (key1[i] >= mid1) ? 0x10000u : 0u;
        }
        c = __reduce_add_sync(~0u, c);
        unsigned c0 = c & 0xFFFFu, c1 = c >> 16;
        if (!d0) {
            if (c0 == (unsigned)KSP) { lo0 = mid0; d0 = true; }
            else if (c0 > (unsigned)KSP) lo0 = mid0;
            else hi0 = mid0 - 1u;
            if (lo0 >= hi0) d0 = true;
        }
        if (!d1) {
            if (c1 == (unsigned)KSP) { lo1 = mid1; d1 = true; }
            else if (c1 > (unsigned)KSP) lo1 = mid1;
            else hi1 = mid1 - 1u;
            if (lo1 >= hi1) d1 = true;
        }
    }
    unsigned T0 = lo0, T1 = lo1;

    // softmax denominators (both rows, interleaved reduces)
    float lsum0 = 0.f, lsum1 = 0.f;
    #pragma unroll
    for (int i = 0; i < 32; ++i) {
        if (key0[i] >= T0) lsum0 += __expf(dec(key0[i]) - lmax0);
        if (key1[i] >= T1) lsum1 += __expf(dec(key1[i]) - lmax1);
    }
    #pragma unroll
    for (int o = 16; o; o >>= 1) {
        lsum0 += __shfl_xor_sync(~0u, lsum0, o);
        lsum1 += __shfl_xor_sync(~0u, lsum1, o);
    }
    float inv0 = 1.f / lsum0, inv1 = 1.f / lsum1;

    // compaction (row0 then row1 — ballots serialize anyway)
    uint2* lst0 = (uint2*)srow0;
    uint2* lst1 = (uint2*)srow1;
    int cnt0 = 0, cnt1 = 0;
    #pragma unroll
    for (int i = 0; i < 32; ++i) {
        bool sel = key0[i] >= T0;
        unsigned mask = __ballot_sync(~0u, sel);
        if (sel) {
            int ofs = cnt0 + __popc(mask & ((1u << lane) - 1u));
            float p = __expf(dec(key0[i]) - lmax0) * inv0;
            if (ofs < 128) {
                uint2 e; e.x = __float_as_uint(p); e.y = (unsigned)(lane + 32*i);
                lst0[ofs] = e;
            }
        }
        cnt0 += __popc(mask);
    }
    #pragma unroll
    for (int i = 0; i < 32; ++i) {
        bool sel = key1[i] >= T1;
        unsigned mask = __ballot_sync(~0u, sel);
        if (sel) {
            int ofs = cnt1 + __popc(mask & ((1u << lane) - 1u));
            float p = __expf(dec(key1[i]) - lmax1) * inv1;
            if (ofs < 128) {
                uint2 e; e.x = __float_as_uint(p); e.y = (unsigned)(lane + 32*i);
                lst1[ofs] = e;
            }
        }
        cnt1 += __popc(mask);
    }
    if (cnt0 > 128) cnt0 = 128;
    if (cnt1 > 128) cnt1 = 128;
    __syncwarp();

    // joint sparse PV: float2 V loads, both rows in flight
    float a00 = 0.f, a01 = 0.f, a10 = 0.f, a11 = 0.f;
    int nmax = cnt0 > cnt1 ? cnt0 : cnt1;
    #pragma unroll 2
    for (int j = 0; j < nmax; ++j) {
        if (j < cnt0) {
            uint2 e = lst0[j];
            float p = __uint_as_float(e.x);
            float2 v = __ldg((const float2*)(Vb + (size_t)e.y * 64) + lane);
            a00 = fmaf(p, v.x, a00);
            a01 = fmaf(p, v.y, a01);
        }
        if (j < cnt1) {
            uint2 e = lst1[j];
            float p = __uint_as_float(e.x);
            float2 v = __ldg((const float2*)(Vb + (size_t)e.y * 64) + lane);
            a10 = fmaf(p, v.x, a10);
            a11 = fmaf(p, v.y, a11);
        }
    }

    // writeback: lane owns dims (2*lane, 2*lane+1)
    int bb = bh >> 4, hh = bh & 15;
    {
        size_t base0 = ((size_t)(bb*1024 + n0 + r0    )) * 1024 + hh*64 + lane*2;
        size_t base1 = ((size_t)(bb*1024 + n0 + r0 + 1)) * 1024 + hh*64 + lane*2;
        bf16 h0, l0, h1, l1;
        bfsplit(a00, h0, l0); bfsplit(a01, h1, l1);
        bf162 ph, pl; ph.x = h0; ph.y = h1; pl.x = l0; pl.y = l1;
        *(bf162*)&g_ath[base0] = ph; *(bf162*)&g_atl[base0] = pl;
        bfsplit(a10, h0, l0); bfsplit(a11, h1, l1);
        ph.x = h0; ph.y = h1; pl.x = l0; pl.y = l1;
        *(bf162*)&g_ath[base1] = ph; *(bf162*)&g_atl[base1] = pl;
    }
}

// ---------------- launch ----------------
extern "C" void kernel_launch(void* const* d_in, const int* in_sizes, int n_in,
                              void* d_out, int out_size)
{
    (void)in_sizes; (void)n_in; (void)out_size;
    const float* x     = (const float*)d_in[0];
    const float* ln1_w = (const float*)d_in[1];
    const float* ln1_b = (const float*)d_in[2];
    const float* qkv_w = (const float*)d_in[3];
    const float* qkv_b = (const float*)d_in[4];
    const float* out_w = (const float*)d_in[5];
    const float* out_b = (const float*)d_in[6];
    const float* ln2_w = (const float*)d_in[7];
    const float* ln2_b = (const float*)d_in[8];
    const float* w1    = (const float*)d_in[9];
    const float* b1    = (const float*)d_in[10];
    const float* w2    = (const float*)d_in[11];
    const float* b2    = (const float*)d_in[12];
    const float* mask1 = (const float*)d_in[13];
    const float* mask2 = (const float*)d_in[14];
    float* out = (float*)d_out;

    void *x1, *xnh, *xnl, *hnh, *hnl, *ath, *atl, *h1h, *h1l,
         *qwh, *qwl, *owh, *owl, *w1h, *w1l, *w2h, *w2l;
    cudaGetSymbolAddress(&x1, g_x1);
    cudaGetSymbolAddress(&xnh, g_xnh); cudaGetSymbolAddress(&xnl, g_xnl);
    cudaGetSymbolAddress(&hnh, g_hnh); cudaGetSymbolAddress(&hnl, g_hnl);
    cudaGetSymbolAddress(&ath, g_ath); cudaGetSymbolAddress(&atl, g_atl);
    cudaGetSymbolAddress(&h1h, g_h1h); cudaGetSymbolAddress(&h1l, g_h1l);
    cudaGetSymbolAddress(&qwh, g_qwh); cudaGetSymbolAddress(&qwl, g_qwl);
    cudaGetSymbolAddress(&owh, g_owh); cudaGetSymbolAddress(&owl, g_owl);
    cudaGetSymbolAddress(&w1h, g_w1h); cudaGetSymbolAddress(&w1l, g_w1l);
    cudaGetSymbolAddress(&w2h, g_w2h); cudaGetSymbolAddress(&w2l, g_w2l);

    cudaFuncSetAttribute(attn_kernel, cudaFuncAttributeMaxDynamicSharedMemorySize, ATTN_SMEM);
    cudaFuncSetAttribute(tc_gemm<0>, cudaFuncAttributeMaxDynamicSharedMemorySize, GSMEM);
    cudaFuncSetAttribute(tc_gemm<1>, cudaFuncAttributeMaxDynamicSharedMemorySize, GSMEM);
    cudaFuncSetAttribute(tc_gemm<2>, cudaFuncAttributeMaxDynamicSharedMemorySize, GSMEM);
    cudaFuncSetAttribute(tc_gemm<3>, cudaFuncAttributeMaxDynamicSharedMemorySize, GSMEM);

    // launch order: [0]cvt4 [1]ln1 [2]gemm0 [3]attn  -> ncu captures attn
    cvt4<<<12288, 256>>>(qkv_w, (bf16*)qwh, (bf16*)qwl, 786432,
                         out_w, (bf16*)owh, (bf16*)owl, 262144,
                         w1,    (bf16*)w1h, (bf16*)w1l, 1048576,
                         w2,    (bf16*)w2h, (bf16*)w2l, 1048576);

    ln_bf16<<<M_, 256>>>(x, ln1_w, ln1_b, (bf16*)xnh, (bf16*)xnl);

    tc_gemm<0><<<dim3(24, 64), 256, GSMEM>>>((bf16*)xnh, (bf16*)xnl,
        (bf16*)qwh, (bf16*)qwl, qkv_b, nullptr, nullptr, nullptr, nullptr, nullptr,
        3*C_, C_);

    attn_kernel<<<BH_*(N_/32), 512, ATTN_SMEM>>>();

    tc_gemm<1><<<dim3(8, 64), 256, GSMEM>>>((bf16*)ath, (bf16*)atl,
        (bf16*)owh, (bf16*)owl, out_b, nullptr, x, (float*)x1, nullptr, nullptr,
        C_, C_);

    ln_bf16<<<M_, 256>>>((float*)x1, ln2_w, ln2_b, (bf16*)hnh, (bf16*)hnl);

    tc_gemm<2><<<dim3(32, 64), 256, GSMEM>>>((bf16*)hnh, (bf16*)hnl,
        (bf16*)w1h, (bf16*)w1l, b1, mask1, nullptr, nullptr, (bf16*)h1h, (bf16*)h1l,
        FF_, C_);

    tc_gemm<3><<<dim3(8, 64), 256, GSMEM>>>((bf16*)h1h, (bf16*)h1l,
        (bf16*)w2h, (bf16*)w2l, b2, mask2, (float*)x1, out, nullptr, nullptr,
        C_, FF_);
}

// round 11
// speedup vs baseline: 1.0186x; 1.0186x over previous
#include <cuda_runtime.h>
#include <cuda_bf16.h>
#include <stdint.h>

#define B_   8
#define N_   1024
#define C_   1024
#define HD_  64
#define FF_  4096
#define BH_  128
#define M_   8192
#define KSP  102

typedef __nv_bfloat16 bf16;
typedef __nv_bfloat162 bf162;

// ---------------- scratch ----------------
__device__ __align__(256) float g_v[(size_t)BH_*N_*HD_];
__device__ __align__(256) float g_x1[(size_t)M_*C_];
__device__ __align__(256) bf16 g_qh[(size_t)BH_*N_*HD_], g_ql[(size_t)BH_*N_*HD_];
__device__ __align__(256) bf16 g_kh[(size_t)BH_*N_*HD_], g_kl[(size_t)BH_*N_*HD_];
__device__ __align__(256) bf16 g_xnh[(size_t)M_*C_],  g_xnl[(size_t)M_*C_];
__device__ __align__(256) bf16 g_hnh[(size_t)M_*C_],  g_hnl[(size_t)M_*C_];
__device__ __align__(256) bf16 g_ath[(size_t)M_*C_],  g_atl[(size_t)M_*C_];
__device__ __align__(256) bf16 g_h1h[(size_t)M_*FF_], g_h1l[(size_t)M_*FF_];
__device__ __align__(256) bf16 g_qwh[(size_t)3*C_*C_], g_qwl[(size_t)3*C_*C_];
__device__ __align__(256) bf16 g_owh[(size_t)C_*C_],   g_owl[(size_t)C_*C_];
__device__ __align__(256) bf16 g_w1h[(size_t)FF_*C_],  g_w1l[(size_t)FF_*C_];
__device__ __align__(256) bf16 g_w2h[(size_t)C_*FF_],  g_w2l[(size_t)C_*FF_];

// ---------------- helpers ----------------
__device__ __forceinline__ uint32_t s2u(const void* p) {
    uint32_t a;
    asm("{ .reg .u64 t; cvta.to.shared.u64 t, %1; cvt.u32.u64 %0, t; }" : "=r"(a) : "l"(p));
    return a;
}
__device__ __forceinline__ void bfsplit(float v, bf16& h, bf16& l) {
    h = __float2bfloat16(v);
    l = __float2bfloat16(v - __bfloat162float(h));
}
__device__ __forceinline__ void ldsm4(uint32_t* r, uint32_t a) {
    asm volatile("ldmatrix.sync.aligned.m8n8.x4.shared.b16 {%0,%1,%2,%3}, [%4];"
        : "=r"(r[0]), "=r"(r[1]), "=r"(r[2]), "=r"(r[3]) : "r"(a));
}
__device__ __forceinline__ void mma16816(float* c, const uint32_t* a, const uint32_t* b) {
    asm volatile("mma.sync.aligned.m16n8k16.row.col.f32.bf16.bf16.f32 "
        "{%0,%1,%2,%3}, {%4,%5,%6,%7}, {%8,%9}, {%0,%1,%2,%3};"
        : "+f"(c[0]), "+f"(c[1]), "+f"(c[2]), "+f"(c[3])
        : "r"(a[0]), "r"(a[1]), "r"(a[2]), "r"(a[3]), "r"(b[0]), "r"(b[1]));
}
#define CP_ASYNC16(s, g) \
    asm volatile("cp.async.cg.shared.global [%0], [%1], 16;" :: "r"(s), "l"(g))
#define CP_COMMIT() asm volatile("cp.async.commit_group;" ::: "memory")
#define CP_WAIT0()  asm volatile("cp.async.wait_group 0;" ::: "memory")

// ---------------- weight split: ALL four weights in ONE launch ------------
__global__ void __launch_bounds__(256)
cvt4(const float* __restrict__ s0, bf16* __restrict__ h0, bf16* __restrict__ l0, int n0,
     const float* __restrict__ s1, bf16* __restrict__ h1, bf16* __restrict__ l1, int n1,
     const float* __restrict__ s2, bf16* __restrict__ h2, bf16* __restrict__ l2, int n2,
     const float* __restrict__ s3, bf16* __restrict__ h3, bf16* __restrict__ l3, int n3)
{
    int i = blockIdx.x * 256 + threadIdx.x;
    const float* s; bf16 *h, *l;
    if (i < n0) { s = s0; h = h0; l = l0; }
    else if ((i -= n0) < n1) { s = s1; h = h1; l = l1; }
    else if ((i -= n1) < n2) { s = s2; h = h2; l = l2; }
    else { i -= n2; if (i >= n3) return; s = s3; h = h3; l = l3; }
    float4 v = ((const float4*)s)[i];
    bf16 a0,a1,a2,a3,b0,b1,b2,b3;
    bfsplit(v.x,a0,b0); bfsplit(v.y,a1,b1); bfsplit(v.z,a2,b2); bfsplit(v.w,a3,b3);
    bf162 p,q;
    p.x=a0;p.y=a1;q.x=a2;q.y=a3; ((bf162*)h)[i*2]=p; ((bf162*)h)[i*2+1]=q;
    p.x=b0;p.y=b1;q.x=b2;q.y=b3; ((bf162*)l)[i*2]=p; ((bf162*)l)[i*2+1]=q;
}

// ---------------- LayerNorm -> bf16 hi/lo ----------------
__global__ void __launch_bounds__(256)
ln_bf16(const float* __restrict__ x, const float* __restrict__ w,
        const float* __restrict__ b, bf16* __restrict__ yh, bf16* __restrict__ yl)
{
    __shared__ float red[16];
    int row = blockIdx.x, t = threadIdx.x;
    float4 v = ((const float4*)(x + (size_t)row * 1024))[t];
    float s  = v.x + v.y + v.z + v.w;
    float ss = v.x*v.x + v.y*v.y + v.z*v.z + v.w*v.w;
    #pragma unroll
    for (int o = 16; o; o >>= 1) {
        s  += __shfl_xor_sync(~0u, s, o);
        ss += __shfl_xor_sync(~0u, ss, o);
    }
    if ((t & 31) == 0) { red[t>>5] = s; red[(t>>5)+8] = ss; }
    __syncthreads();
    if (t == 0) {
        float ts=0.f, tss=0.f;
        #pragma unroll
        for (int i = 0; i < 8; ++i) { ts += red[i]; tss += red[i+8]; }
        float mu = ts * (1.f/1024.f);
        red[0] = mu; red[1] = rsqrtf(tss*(1.f/1024.f) - mu*mu + 1e-5f);
    }
    __syncthreads();
    float mu = red[0], rs = red[1];
    float4 wv = ((const float4*)w)[t];
    float4 bv = ((const float4*)b)[t];
    float o0 = (v.x-mu)*rs*wv.x + bv.x, o1 = (v.y-mu)*rs*wv.y + bv.y;
    float o2 = (v.z-mu)*rs*wv.z + bv.z, o3 = (v.w-mu)*rs*wv.w + bv.w;
    bf16 h0,h1,h2,h3,l0,l1,l2,l3;
    bfsplit(o0,h0,l0); bfsplit(o1,h1,l1); bfsplit(o2,h2,l2); bfsplit(o3,h3,l3);
    size_t oi = ((size_t)row*1024 + t*4) >> 1;
    bf162 pa, pb;
    pa.x=h0;pa.y=h1;pb.x=h2;pb.y=h3; ((bf162*)yh)[oi]=pa; ((bf162*)yh)[oi+1]=pb;
    pa.x=l0;pa.y=l1;pb.x=l2;pb.y=l3; ((bf162*)yl)[oi]=pa; ((bf162*)yl)[oi+1]=pb;
}

// ---- HMMA GEMM: 128x128 tile, 256 thr, 2-stage, 2 CTAs/SM, bf16x3 ----
#define ATILE_B  10240
#define STAGE_B  40960
#define GSMEM    (2*STAGE_B)

__device__ __forceinline__ void issue_stage(
    const bf16* __restrict__ Ah, const bf16* __restrict__ Al,
    const bf16* __restrict__ Bh, const bf16* __restrict__ Bl,
    uint32_t sbase, int bm, int bn, int ko, int K, int tid)
{
    #pragma unroll
    for (int i = 0; i < 8; ++i) {
        int lin = tid + (i << 8);
        int tile = lin >> 9;
        int wit = lin & 511;
        int r = wit >> 2, ch = wit & 3;
        const bf16* gp;
        if      (tile == 0) gp = Ah + (size_t)(bm + r) * K + ko + ch*8;
        else if (tile == 1) gp = Al + (size_t)(bm + r) * K + ko + ch*8;
        else if (tile == 2) gp = Bh + (size_t)(bn + r) * K + ko + ch*8;
        else                gp = Bl + (size_t)(bn + r) * K + ko + ch*8;
        CP_ASYNC16(sbase + tile*ATILE_B + r*80 + ch*16, gp);
    }
    CP_COMMIT();
}

template<int EPI>
__global__ void __launch_bounds__(256, 2)
tc_gemm(const bf16* __restrict__ Ah, const bf16* __restrict__ Al,
        const bf16* __restrict__ Bh, const bf16* __restrict__ Bl,
        const float* __restrict__ bias, const float* __restrict__ aux,
        const float* __restrict__ res, float* __restrict__ outf,
        bf16* __restrict__ outh, bf16* __restrict__ outl, int N, int K)
{
    extern __shared__ char smem[];
    uint32_t sb = s2u(smem);
    const int tid = threadIdx.x, lane = tid & 31, wid = tid >> 5;
    const int wm = wid & 3, wn = wid >> 2;
    const int bm = blockIdx.y << 7, bn = blockIdx.x << 7;

    float acc[2][8][4];
    #pragma unroll
    for (int i = 0; i < 2; ++i)
        #pragma unroll
        for (int j = 0; j < 8; ++j)
            #pragma unroll
            for (int q = 0; q < 4; ++q) acc[i][j][q] = 0.f;

    const int ktn = K >> 5;
    issue_stage(Ah, Al, Bh, Bl, sb, bm, bn, 0, K, tid);

    const int a_ro = (lane & 15);
    const int a_ko = (lane >> 4) * 8;
    const int b_rp = ((lane >> 4) & 1) * 8 + (lane & 7);
    const int b_ko = ((lane >> 3) & 1) * 8;

    for (int kt = 0; kt < ktn; ++kt) {
        CP_WAIT0();
        __syncthreads();
        if (kt + 1 < ktn)
            issue_stage(Ah, Al, Bh, Bl, sb + ((kt + 1) & 1) * STAGE_B,
                        bm, bn, (kt + 1) * 32, K, tid);
        uint32_t st = sb + (kt & 1) * STAGE_B;
        #pragma unroll
        for (int ks = 0; ks < 2; ++ks) {
            uint32_t ahi[2][4], alo[2][4], bhi[4][4], blo[4][4];
            #pragma unroll
            for (int mf = 0; mf < 2; ++mf)
                ldsm4(ahi[mf], st + (wm*32 + mf*16 + a_ro)*80 + (ks*16 + a_ko)*2);
            #pragma unroll
            for (int np = 0; np < 4; ++np)
                ldsm4(bhi[np], st + 2*ATILE_B + (wn*64 + np*16 + b_rp)*80 + (ks*16 + b_ko)*2);
            #pragma unroll
            for (int np = 0; np < 4; ++np)
                #pragma unroll
                for (int mf = 0; mf < 2; ++mf) {
                    mma16816(acc[mf][np*2  ], ahi[mf], &bhi[np][0]);
                    mma16816(acc[mf][np*2+1], ahi[mf], &bhi[np][2]);
                }
            #pragma unroll
            for (int np = 0; np < 4; ++np)
                ldsm4(blo[np], st + 2*ATILE_B + ATILE_B + (wn*64 + np*16 + b_rp)*80 + (ks*16 + b_ko)*2);
            #pragma unroll
            for (int np = 0; np < 4; ++np)
                #pragma unroll
                for (int mf = 0; mf < 2; ++mf) {
                    mma16816(acc[mf][np*2  ], ahi[mf], &blo[np][0]);
                    mma16816(acc[mf][np*2+1], ahi[mf], &blo[np][2]);
                }
            #pragma unroll
            for (int mf = 0; mf < 2; ++mf)
                ldsm4(alo[mf], st + ATILE_B + (wm*32 + mf*16 + a_ro)*80 + (ks*16 + a_ko)*2);
            #pragma unroll
            for (int np = 0; np < 4; ++np)
                #pragma unroll
                for (int mf = 0; mf < 2; ++mf) {
                    mma16816(acc[mf][np*2  ], alo[mf], &bhi[np][0]);
                    mma16816(acc[mf][np*2+1], alo[mf], &bhi[np][2]);
                }
        }
    }

    const int tr = lane >> 2;
    const int tc = (lane & 3) * 2;
    #pragma unroll
    for (int mf = 0; mf < 2; ++mf) {
        #pragma unroll
        for (int nf = 0; nf < 8; ++nf) {
            int gj = bn + wn*64 + nf*8 + tc;
            float2 b2 = *(const float2*)&bias[gj];
            #pragma unroll
            for (int h = 0; h < 2; ++h) {
                int gi = bm + wm*32 + mf*16 + tr + h*8;
                float v0 = acc[mf][nf][h*2]   + b2.x;
                float v1 = acc[mf][nf][h*2+1] + b2.y;
                size_t off = (size_t)gi * N + gj;
                if (EPI == 0) {
                    int wh = gj >> 10, hh = (gj >> 6) & 15, d = gj & 63;
                    int bb = gi >> 10, nn = gi & 1023;
                    size_t idx = (((size_t)(bb*16 + hh))*1024 + nn)*64 + d;
                    if (wh == 2) {
                        float2 o; o.x = v0; o.y = v1;
                        *(float2*)&g_v[idx] = o;
                    } else {
                        bf16 h0,l0,h1,l1;
                        bfsplit(v0,h0,l0); bfsplit(v1,h1,l1);
                        bf162 ph, pl; ph.x=h0; ph.y=h1; pl.x=l0; pl.y=l1;
                        if (wh == 0) { *(bf162*)&g_qh[idx]=ph; *(bf162*)&g_ql[idx]=pl; }
                        else         { *(bf162*)&g_kh[idx]=ph; *(bf162*)&g_kl[idx]=pl; }
                    }
                } else if (EPI == 1) {
                    float2 rr = *(const float2*)&res[off];
                    float2 o; o.x = v0 + rr.x; o.y = v1 + rr.y;
                    *(float2*)&outf[off] = o;
                } else if (EPI == 2) {
                    float2 m = *(const float2*)&aux[off];
                    v0 = (m.x > 0.5f) ? fmaxf(v0, 0.f) : 0.f;
                    v1 = (m.y > 0.5f) ? fmaxf(v1, 0.f) : 0.f;
                    bf16 h0,l0,h1,l1;
                    bfsplit(v0,h0,l0); bfsplit(v1,h1,l1);
                    bf162 p; p.x=h0; p.y=h1; *(bf162*)&outh[off] = p;
                    p.x=l0; p.y=l1;          *(bf162*)&outl[off] = p;
                } else {
                    float2 m  = *(const float2*)&aux[off];
                    float2 rr = *(const float2*)&res[off];
                    float2 o;
                    o.x = rr.x + ((m.x > 0.5f) ? v0 : 0.f);
                    o.y = rr.y + ((m.y > 0.5f) ? v1 : 0.f);
                    *(float2*)&outf[off] = o;
                }
            }
        }
    }
}

// ------ sparse attention: 16 q-rows/block, 2 blocks/SM, HMMA scores -------
// smem: Q hi/lo 4608 | K hi/lo 36864 (single buffer) | sS 16x1034 f32 (66176)
#define SS_STR  1034
#define SS_OFF  10368              /* (4608+36864)/4 */
#define ATTN_SMEM 107648

__device__ __forceinline__ void issue_k(uint32_t sb, size_t bhoff, int kt, int tid) {
    #pragma unroll
    for (int i = 0; i < 8; ++i) {
        int lin = tid + (i << 8);
        int tile = lin >> 10, wit = lin & 1023;
        int r = wit >> 3, ch = wit & 7;
        const bf16* gsrc = (tile ? g_kl : g_kh) + bhoff + (size_t)(kt*128 + r)*64 + ch*8;
        CP_ASYNC16(sb + 4608 + tile*18432 + r*144 + ch*16, gsrc);
    }
    CP_COMMIT();
}

__device__ __forceinline__ float dec(unsigned ub) {
    unsigned fb = ub ^ ((ub & 0x80000000u) ? 0x80000000u : 0xFFFFFFFFu);
    return __uint_as_float(fb);
}

__global__ void __launch_bounds__(256, 2)
attn_kernel()
{
    extern __shared__ char smraw[];
    float* smf = (float*)smraw;
    uint32_t sb = s2u(smraw);

    int blk = blockIdx.x, bh = blk >> 6, n0 = (blk & 63) << 4;
    int tid = threadIdx.x, lane = tid & 31, w = tid >> 5;   // w: 0..7
    const size_t bhoff = (size_t)bh * 65536;

    // load Q tile (16 rows, bf16 hi/lo)
    {
        int tile = tid >> 7, wit = tid & 127, r = wit >> 3, ch = wit & 7;
        const bf16* gsrc = (tile ? g_ql : g_qh) + bhoff + (size_t)(n0 + r)*64 + ch*8;
        *(uint4*)(smraw + tile*2304 + r*144 + ch*16) = *(const uint4*)gsrc;
    }
    issue_k(sb, bhoff, 0, tid);
    __syncthreads();

    const int a_ro = lane & 15, a_ko = (lane >> 4) * 8;
    const int b_rp = ((lane >> 4) & 1) * 8 + (lane & 7);
    const int b_ko = ((lane >> 3) & 1) * 8;
    uint32_t qhi[4][4], qlo[4][4];
    #pragma unroll
    for (int ks = 0; ks < 4; ++ks) {
        uint32_t qa = sb + a_ro*144 + (ks*16 + a_ko)*2;
        ldsm4(qhi[ks], qa);
        ldsm4(qlo[ks], qa + 2304);
    }
    const int tr = lane >> 2, tc = (lane & 3) * 2;

    // ---- phase 1: scores via HMMA (single-buffered K; cross-block overlap) ----
    for (int kt = 0; kt < 8; ++kt) {
        CP_WAIT0();
        __syncthreads();
        uint32_t kb = sb + 4608;
        float acc[2][4];
        #pragma unroll
        for (int nf = 0; nf < 2; ++nf)
            #pragma unroll
            for (int q = 0; q < 4; ++q) acc[nf][q] = 0.f;
        #pragma unroll
        for (int ks = 0; ks < 4; ++ks) {
            uint32_t bd = kb + (w*16 + b_rp)*144 + (ks*16 + b_ko)*2;
            uint32_t bhi[4], blo[4];
            ldsm4(bhi, bd);
            ldsm4(blo, bd + 18432);
            mma16816(acc[0], qhi[ks], &bhi[0]);
            mma16816(acc[1], qhi[ks], &bhi[2]);
            mma16816(acc[0], qhi[ks], &blo[0]);
            mma16816(acc[1], qhi[ks], &blo[2]);
            mma16816(acc[0], qlo[ks], &bhi[0]);
            mma16816(acc[1], qlo[ks], &bhi[2]);
        }
        __syncthreads();                 // all warps done reading K buffer
        if (kt < 7) issue_k(sb, bhoff, kt + 1, tid);
        #pragma unroll
        for (int nf = 0; nf < 2; ++nf) {
            int key = kt*128 + w*16 + nf*8 + tc;
            float2 o;
            o.x = acc[nf][0]*0.125f; o.y = acc[nf][1]*0.125f;
            *(float2*)&smf[SS_OFF + tr*SS_STR + key] = o;
            o.x = acc[nf][2]*0.125f; o.y = acc[nf][3]*0.125f;
            *(float2*)&smf[SS_OFF + (tr+8)*SS_STR + key] = o;
        }
    }
    __syncthreads();

    // ---- per-row: early-exit top-k, softmax, compaction, sparse PV ----
    int r0 = 2 * w;
    float o00=0, o01=0, o10=0, o11=0;
    const float* Vb = g_v + bhoff;
    #pragma unroll 1
    for (int rr = 0; rr < 2; ++rr) {
        float* srow = &smf[SS_OFF + (r0 + rr) * SS_STR];
        unsigned key[32];
        float lmax = -3.4e38f;
        #pragma unroll
        for (int i = 0; i < 32; ++i) {
            float s = srow[lane + 32*i];
            lmax = fmaxf(lmax, s);
            unsigned ub = __float_as_uint(s);
            key[i] = ub ^ (((unsigned)((int)ub >> 31)) | 0x80000000u);
        }
        #pragma unroll
        for (int o = 16; o; o >>= 1) lmax = fmaxf(lmax, __shfl_xor_sync(~0u, lmax, o));

        unsigned T;
        {
            unsigned lo = 0u, hi = 0xFFFFFFFFu;
            while (lo < hi) {
                unsigned mid = lo + (unsigned)(((unsigned long long)(hi - lo) + 1ull) >> 1);
                unsigned c = 0;
                #pragma unroll
                for (int i = 0; i < 32; ++i) c += (key[i] >= mid) ? 1u : 0u;
                c = __reduce_add_sync(~0u, c);
                if (c == (unsigned)KSP) { lo = mid; break; }
                if (c > (unsigned)KSP) lo = mid; else hi = mid - 1u;
            }
            T = lo;
        }

        float lsum = 0.f;
        #pragma unroll
        for (int i = 0; i < 32; ++i) {
            if (key[i] >= T) lsum += __expf(dec(key[i]) - lmax);
        }
        #pragma unroll
        for (int o = 16; o; o >>= 1) lsum += __shfl_xor_sync(~0u, lsum, o);
        float inv = 1.f / lsum;

        uint2* lst = (uint2*)srow;
        int cnt = 0;
        #pragma unroll
        for (int i = 0; i < 32; ++i) {
            bool sel = key[i] >= T;
            unsigned mask = __ballot_sync(~0u, sel);
            if (sel) {
                int ofs = cnt + __popc(mask & ((1u << lane) - 1u));
                float p = __expf(dec(key[i]) - lmax) * inv;
                if (ofs < 128) {
                    uint2 e; e.x = __float_as_uint(p); e.y = (unsigned)(lane + 32*i);
                    lst[ofs] = e;
                }
            }
            cnt += __popc(mask);
        }
        if (cnt > 128) cnt = 128;
        __syncwarp();

        float a0 = 0.f, a1 = 0.f;
        #pragma unroll 4
        for (int j = 0; j < cnt; ++j) {
            uint2 e = lst[j];
            float p = __uint_as_float(e.x);
            const float* vr = Vb + (size_t)e.y * 64;
            a0 = fmaf(p, __ldg(vr + lane),      a0);
            a1 = fmaf(p, __ldg(vr + lane + 32), a1);
        }
        if (rr == 0) { o00 = a0; o01 = a1; } else { o10 = a0; o11 = a1; }
    }

    int bb = bh >> 4, hh = bh & 15;
    #pragma unroll
    for (int rr = 0; rr < 2; ++rr) {
        size_t base = ((size_t)(bb*1024 + n0 + r0 + rr)) * 1024 + hh*64;
        bf16 h, l;
        bfsplit(rr ? o10 : o00, h, l);
        g_ath[base + lane] = h; g_atl[base + lane] = l;
        bfsplit(rr ? o11 : o01, h, l);
        g_ath[base + lane + 32] = h; g_atl[base + lane + 32] = l;
    }
}

// ---------------- launch ----------------
extern "C" void kernel_launch(void* const* d_in, const int* in_sizes, int n_in,
                              void* d_out, int out_size)
{
    (void)in_sizes; (void)n_in; (void)out_size;
    const float* x     = (const float*)d_in[0];
    const float* ln1_w = (const float*)d_in[1];
    const float* ln1_b = (const float*)d_in[2];
    const float* qkv_w = (const float*)d_in[3];
    const float* qkv_b = (const float*)d_in[4];
    const float* out_w = (const float*)d_in[5];
    const float* out_b = (const float*)d_in[6];
    const float* ln2_w = (const float*)d_in[7];
    const float* ln2_b = (const float*)d_in[8];
    const float* w1    = (const float*)d_in[9];
    const float* b1    = (const float*)d_in[10];
    const float* w2    = (const float*)d_in[11];
    const float* b2    = (const float*)d_in[12];
    const float* mask1 = (const float*)d_in[13];
    const float* mask2 = (const float*)d_in[14];
    float* out = (float*)d_out;

    void *x1, *xnh, *xnl, *hnh, *hnl, *ath, *atl, *h1h, *h1l,
         *qwh, *qwl, *owh, *owl, *w1h, *w1l, *w2h, *w2l;
    cudaGetSymbolAddress(&x1, g_x1);
    cudaGetSymbolAddress(&xnh, g_xnh); cudaGetSymbolAddress(&xnl, g_xnl);
    cudaGetSymbolAddress(&hnh, g_hnh); cudaGetSymbolAddress(&hnl, g_hnl);
    cudaGetSymbolAddress(&ath, g_ath); cudaGetSymbolAddress(&atl, g_atl);
    cudaGetSymbolAddress(&h1h, g_h1h); cudaGetSymbolAddress(&h1l, g_h1l);
    cudaGetSymbolAddress(&qwh, g_qwh); cudaGetSymbolAddress(&qwl, g_qwl);
    cudaGetSymbolAddress(&owh, g_owh); cudaGetSymbolAddress(&owl, g_owl);
    cudaGetSymbolAddress(&w1h, g_w1h); cudaGetSymbolAddress(&w1l, g_w1l);
    cudaGetSymbolAddress(&w2h, g_w2h); cudaGetSymbolAddress(&w2l, g_w2l);

    cudaFuncSetAttribute(attn_kernel, cudaFuncAttributeMaxDynamicSharedMemorySize, ATTN_SMEM);
    cudaFuncSetAttribute(tc_gemm<0>, cudaFuncAttributeMaxDynamicSharedMemorySize, GSMEM);
    cudaFuncSetAttribute(tc_gemm<1>, cudaFuncAttributeMaxDynamicSharedMemorySize, GSMEM);
    cudaFuncSetAttribute(tc_gemm<2>, cudaFuncAttributeMaxDynamicSharedMemorySize, GSMEM);
    cudaFuncSetAttribute(tc_gemm<3>, cudaFuncAttributeMaxDynamicSharedMemorySize, GSMEM);

    // launch order: [0]cvt4 [1]ln1 [2]gemm0 [3]attn  -> ncu captures attn
    cvt4<<<12288, 256>>>(qkv_w, (bf16*)qwh, (bf16*)qwl, 786432,
                         out_w, (bf16*)owh, (bf16*)owl, 262144,
                         w1,    (bf16*)w1h, (bf16*)w1l, 1048576,
                         w2,    (bf16*)w2h, (bf16*)w2l, 1048576);

    ln_bf16<<<M_, 256>>>(x, ln1_w, ln1_b, (bf16*)xnh, (bf16*)xnl);

    tc_gemm<0><<<dim3(24, 64), 256, GSMEM>>>((bf16*)xnh, (bf16*)xnl,
        (bf16*)qwh, (bf16*)qwl, qkv_b, nullptr, nullptr, nullptr, nullptr, nullptr,
        3*C_, C_);

    attn_kernel<<<BH_*(N_/16), 256, ATTN_SMEM>>>();

    tc_gemm<1><<<dim3(8, 64), 256, GSMEM>>>((bf16*)ath, (bf16*)atl,
        (bf16*)owh, (bf16*)owl, out_b, nullptr, x, (float*)x1, nullptr, nullptr,
        C_, C_);

    ln_bf16<<<M_, 256>>>((float*)x1, ln2_w, ln2_b, (bf16*)hnh, (bf16*)hnl);

    tc_gemm<2><<<dim3(32, 64), 256, GSMEM>>>((bf16*)hnh, (bf16*)hnl,
        (bf16*)w1h, (bf16*)w1l, b1, mask1, nullptr, nullptr, (bf16*)h1h, (bf16*)h1l,
        FF_, C_);

    tc_gemm<3><<<dim3(8, 64), 256, GSMEM>>>((bf16*)h1h, (bf16*)h1l,
        (bf16*)w2h, (bf16*)w2l, b2, mask2, (float*)x1, out, nullptr, nullptr,
        C_, FF_);
}

// round 12
// speedup vs baseline: 1.0289x; 1.0102x over previous
#include <cuda_runtime.h>
#include <cuda_bf16.h>
#include <cuda_fp16.h>
#include <stdint.h>

#define B_   8
#define N_   1024
#define C_   1024
#define HD_  64
#define FF_  4096
#define BH_  128
#define M_   8192
#define KSP  102

typedef __nv_bfloat16 bf16;
typedef __nv_bfloat162 bf162;

// ---------------- scratch ----------------
__device__ __align__(256) __half g_v[(size_t)BH_*N_*HD_];
__device__ __align__(256) float g_x1[(size_t)M_*C_];
__device__ __align__(256) bf16 g_qh[(size_t)BH_*N_*HD_], g_ql[(size_t)BH_*N_*HD_];
__device__ __align__(256) bf16 g_kh[(size_t)BH_*N_*HD_], g_kl[(size_t)BH_*N_*HD_];
__device__ __align__(256) bf16 g_xnh[(size_t)M_*C_],  g_xnl[(size_t)M_*C_];
__device__ __align__(256) bf16 g_hnh[(size_t)M_*C_],  g_hnl[(size_t)M_*C_];
__device__ __align__(256) bf16 g_ath[(size_t)M_*C_],  g_atl[(size_t)M_*C_];
__device__ __align__(256) bf16 g_h1h[(size_t)M_*FF_], g_h1l[(size_t)M_*FF_];
__device__ __align__(256) bf16 g_qwh[(size_t)3*C_*C_], g_qwl[(size_t)3*C_*C_];
__device__ __align__(256) bf16 g_owh[(size_t)C_*C_],   g_owl[(size_t)C_*C_];
__device__ __align__(256) bf16 g_w1h[(size_t)FF_*C_],  g_w1l[(size_t)FF_*C_];
__device__ __align__(256) bf16 g_w2h[(size_t)C_*FF_],  g_w2l[(size_t)C_*FF_];

// ---------------- helpers ----------------
__device__ __forceinline__ uint32_t s2u(const void* p) {
    uint32_t a;
    asm("{ .reg .u64 t; cvta.to.shared.u64 t, %1; cvt.u32.u64 %0, t; }" : "=r"(a) : "l"(p));
    return a;
}
__device__ __forceinline__ void bfsplit(float v, bf16& h, bf16& l) {
    h = __float2bfloat16(v);
    l = __float2bfloat16(v - __bfloat162float(h));
}
__device__ __forceinline__ void ldsm4(uint32_t* r, uint32_t a) {
    asm volatile("ldmatrix.sync.aligned.m8n8.x4.shared.b16 {%0,%1,%2,%3}, [%4];"
        : "=r"(r[0]), "=r"(r[1]), "=r"(r[2]), "=r"(r[3]) : "r"(a));
}
__device__ __forceinline__ void mma16816(float* c, const uint32_t* a, const uint32_t* b) {
    asm volatile("mma.sync.aligned.m16n8k16.row.col.f32.bf16.bf16.f32 "
        "{%0,%1,%2,%3}, {%4,%5,%6,%7}, {%8,%9}, {%0,%1,%2,%3};"
        : "+f"(c[0]), "+f"(c[1]), "+f"(c[2]), "+f"(c[3])
        : "r"(a[0]), "r"(a[1]), "r"(a[2]), "r"(a[3]), "r"(b[0]), "r"(b[1]));
}
#define CP_ASYNC16(s, g) \
    asm volatile("cp.async.cg.shared.global [%0], [%1], 16;" :: "r"(s), "l"(g))
#define CP_COMMIT() asm volatile("cp.async.commit_group;" ::: "memory")
#define CP_WAIT0()  asm volatile("cp.async.wait_group 0;" ::: "memory")

// ---------------- weight split: ALL four weights in ONE launch ------------
__global__ void __launch_bounds__(256)
cvt4(const float* __restrict__ s0, bf16* __restrict__ h0, bf16* __restrict__ l0, int n0,
     const float* __restrict__ s1, bf16* __restrict__ h1, bf16* __restrict__ l1, int n1,
     const float* __restrict__ s2, bf16* __restrict__ h2, bf16* __restrict__ l2, int n2,
     const float* __restrict__ s3, bf16* __restrict__ h3, bf16* __restrict__ l3, int n3)
{
    int i = blockIdx.x * 256 + threadIdx.x;
    const float* s; bf16 *h, *l;
    if (i < n0) { s = s0; h = h0; l = l0; }
    else if ((i -= n0) < n1) { s = s1; h = h1; l = l1; }
    else if ((i -= n1) < n2) { s = s2; h = h2; l = l2; }
    else { i -= n2; if (i >= n3) return; s = s3; h = h3; l = l3; }
    float4 v = ((const float4*)s)[i];
    bf16 a0,a1,a2,a3,b0,b1,b2,b3;
    bfsplit(v.x,a0,b0); bfsplit(v.y,a1,b1); bfsplit(v.z,a2,b2); bfsplit(v.w,a3,b3);
    bf162 p,q;
    p.x=a0;p.y=a1;q.x=a2;q.y=a3; ((bf162*)h)[i*2]=p; ((bf162*)h)[i*2+1]=q;
    p.x=b0;p.y=b1;q.x=b2;q.y=b3; ((bf162*)l)[i*2]=p; ((bf162*)l)[i*2+1]=q;
}

// ---------------- LayerNorm -> bf16 hi/lo ----------------
__global__ void __launch_bounds__(256)
ln_bf16(const float* __restrict__ x, const float* __restrict__ w,
        const float* __restrict__ b, bf16* __restrict__ yh, bf16* __restrict__ yl)
{
    __shared__ float red[16];
    int row = blockIdx.x, t = threadIdx.x;
    float4 v = ((const float4*)(x + (size_t)row * 1024))[t];
    float s  = v.x + v.y + v.z + v.w;
    float ss = v.x*v.x + v.y*v.y + v.z*v.z + v.w*v.w;
    #pragma unroll
    for (int o = 16; o; o >>= 1) {
        s  += __shfl_xor_sync(~0u, s, o);
        ss += __shfl_xor_sync(~0u, ss, o);
    }
    if ((t & 31) == 0) { red[t>>5] = s; red[(t>>5)+8] = ss; }
    __syncthreads();
    if (t == 0) {
        float ts=0.f, tss=0.f;
        #pragma unroll
        for (int i = 0; i < 8; ++i) { ts += red[i]; tss += red[i+8]; }
        float mu = ts * (1.f/1024.f);
        red[0] = mu; red[1] = rsqrtf(tss*(1.f/1024.f) - mu*mu + 1e-5f);
    }
    __syncthreads();
    float mu = red[0], rs = red[1];
    float4 wv = ((const float4*)w)[t];
    float4 bv = ((const float4*)b)[t];
    float o0 = (v.x-mu)*rs*wv.x + bv.x, o1 = (v.y-mu)*rs*wv.y + bv.y;
    float o2 = (v.z-mu)*rs*wv.z + bv.z, o3 = (v.w-mu)*rs*wv.w + bv.w;
    bf16 h0,h1,h2,h3,l0,l1,l2,l3;
    bfsplit(o0,h0,l0); bfsplit(o1,h1,l1); bfsplit(o2,h2,l2); bfsplit(o3,h3,l3);
    size_t oi = ((size_t)row*1024 + t*4) >> 1;
    bf162 pa, pb;
    pa.x=h0;pa.y=h1;pb.x=h2;pb.y=h3; ((bf162*)yh)[oi]=pa; ((bf162*)yh)[oi+1]=pb;
    pa.x=l0;pa.y=l1;pb.x=l2;pb.y=l3; ((bf162*)yl)[oi]=pa; ((bf162*)yl)[oi+1]=pb;
}

// ---- HMMA GEMM: 128x128 tile, 256 thr, 2-stage, 2 CTAs/SM, bf16x3 ----
#define ATILE_B  10240
#define STAGE_B  40960
#define GSMEM    (2*STAGE_B)

__device__ __forceinline__ void issue_stage(
    const bf16* __restrict__ Ah, const bf16* __restrict__ Al,
    const bf16* __restrict__ Bh, const bf16* __restrict__ Bl,
    uint32_t sbase, int bm, int bn, int ko, int K, int tid)
{
    #pragma unroll
    for (int i = 0; i < 8; ++i) {
        int lin = tid + (i << 8);
        int tile = lin >> 9;
        int wit = lin & 511;
        int r = wit >> 2, ch = wit & 3;
        const bf16* gp;
        if      (tile == 0) gp = Ah + (size_t)(bm + r) * K + ko + ch*8;
        else if (tile == 1) gp = Al + (size_t)(bm + r) * K + ko + ch*8;
        else if (tile == 2) gp = Bh + (size_t)(bn + r) * K + ko + ch*8;
        else                gp = Bl + (size_t)(bn + r) * K + ko + ch*8;
        CP_ASYNC16(sbase + tile*ATILE_B + r*80 + ch*16, gp);
    }
    CP_COMMIT();
}

template<int EPI>
__global__ void __launch_bounds__(256, 2)
tc_gemm(const bf16* __restrict__ Ah, const bf16* __restrict__ Al,
        const bf16* __restrict__ Bh, const bf16* __restrict__ Bl,
        const float* __restrict__ bias, const float* __restrict__ aux,
        const float* __restrict__ res, float* __restrict__ outf,
        bf16* __restrict__ outh, bf16* __restrict__ outl, int N, int K)
{
    extern __shared__ char smem[];
    uint32_t sb = s2u(smem);
    const int tid = threadIdx.x, lane = tid & 31, wid = tid >> 5;
    const int wm = wid & 3, wn = wid >> 2;
    const int bm = blockIdx.y << 7, bn = blockIdx.x << 7;

    float acc[2][8][4];
    #pragma unroll
    for (int i = 0; i < 2; ++i)
        #pragma unroll
        for (int j = 0; j < 8; ++j)
            #pragma unroll
            for (int q = 0; q < 4; ++q) acc[i][j][q] = 0.f;

    const int ktn = K >> 5;
    issue_stage(Ah, Al, Bh, Bl, sb, bm, bn, 0, K, tid);

    const int a_ro = (lane & 15);
    const int a_ko = (lane >> 4) * 8;
    const int b_rp = ((lane >> 4) & 1) * 8 + (lane & 7);
    const int b_ko = ((lane >> 3) & 1) * 8;

    for (int kt = 0; kt < ktn; ++kt) {
        CP_WAIT0();
        __syncthreads();
        if (kt + 1 < ktn)
            issue_stage(Ah, Al, Bh, Bl, sb + ((kt + 1) & 1) * STAGE_B,
                        bm, bn, (kt + 1) * 32, K, tid);
        uint32_t st = sb + (kt & 1) * STAGE_B;
        #pragma unroll
        for (int ks = 0; ks < 2; ++ks) {
            uint32_t ahi[2][4], alo[2][4], bhi[4][4], blo[4][4];
            #pragma unroll
            for (int mf = 0; mf < 2; ++mf)
                ldsm4(ahi[mf], st + (wm*32 + mf*16 + a_ro)*80 + (ks*16 + a_ko)*2);
            #pragma unroll
            for (int np = 0; np < 4; ++np)
                ldsm4(bhi[np], st + 2*ATILE_B + (wn*64 + np*16 + b_rp)*80 + (ks*16 + b_ko)*2);
            #pragma unroll
            for (int np = 0; np < 4; ++np)
                #pragma unroll
                for (int mf = 0; mf < 2; ++mf) {
                    mma16816(acc[mf][np*2  ], ahi[mf], &bhi[np][0]);
                    mma16816(acc[mf][np*2+1], ahi[mf], &bhi[np][2]);
                }
            #pragma unroll
            for (int np = 0; np < 4; ++np)
                ldsm4(blo[np], st + 2*ATILE_B + ATILE_B + (wn*64 + np*16 + b_rp)*80 + (ks*16 + b_ko)*2);
            #pragma unroll
            for (int np = 0; np < 4; ++np)
                #pragma unroll
                for (int mf = 0; mf < 2; ++mf) {
                    mma16816(acc[mf][np*2  ], ahi[mf], &blo[np][0]);
                    mma16816(acc[mf][np*2+1], ahi[mf], &blo[np][2]);
                }
            #pragma unroll
            for (int mf = 0; mf < 2; ++mf)
                ldsm4(alo[mf], st + ATILE_B + (wm*32 + mf*16 + a_ro)*80 + (ks*16 + a_ko)*2);
            #pragma unroll
            for (int np = 0; np < 4; ++np)
                #pragma unroll
                for (int mf = 0; mf < 2; ++mf) {
                    mma16816(acc[mf][np*2  ], alo[mf], &bhi[np][0]);
                    mma16816(acc[mf][np*2+1], alo[mf], &bhi[np][2]);
                }
        }
    }

    const int tr = lane >> 2;
    const int tc = (lane & 3) * 2;
    #pragma unroll
    for (int mf = 0; mf < 2; ++mf) {
        #pragma unroll
        for (int nf = 0; nf < 8; ++nf) {
            int gj = bn + wn*64 + nf*8 + tc;
            float2 b2 = *(const float2*)&bias[gj];
            #pragma unroll
            for (int h = 0; h < 2; ++h) {
                int gi = bm + wm*32 + mf*16 + tr + h*8;
                float v0 = acc[mf][nf][h*2]   + b2.x;
                float v1 = acc[mf][nf][h*2+1] + b2.y;
                size_t off = (size_t)gi * N + gj;
                if (EPI == 0) {
                    int wh = gj >> 10, hh = (gj >> 6) & 15, d = gj & 63;
                    int bb = gi >> 10, nn = gi & 1023;
                    size_t idx = (((size_t)(bb*16 + hh))*1024 + nn)*64 + d;
                    if (wh == 2) {
                        *(__half2*)&g_v[idx] = __floats2half2_rn(v0, v1);
                    } else {
                        bf16 h0,l0,h1,l1;
                        bfsplit(v0,h0,l0); bfsplit(v1,h1,l1);
                        bf162 ph, pl; ph.x=h0; ph.y=h1; pl.x=l0; pl.y=l1;
                        if (wh == 0) { *(bf162*)&g_qh[idx]=ph; *(bf162*)&g_ql[idx]=pl; }
                        else         { *(bf162*)&g_kh[idx]=ph; *(bf162*)&g_kl[idx]=pl; }
                    }
                } else if (EPI == 1) {
                    float2 rr = *(const float2*)&res[off];
                    float2 o; o.x = v0 + rr.x; o.y = v1 + rr.y;
                    *(float2*)&outf[off] = o;
                } else if (EPI == 2) {
                    float2 m = *(const float2*)&aux[off];
                    v0 = (m.x > 0.5f) ? fmaxf(v0, 0.f) : 0.f;
                    v1 = (m.y > 0.5f) ? fmaxf(v1, 0.f) : 0.f;
                    bf16 h0,l0,h1,l1;
                    bfsplit(v0,h0,l0); bfsplit(v1,h1,l1);
                    bf162 p; p.x=h0; p.y=h1; *(bf162*)&outh[off] = p;
                    p.x=l0; p.y=l1;          *(bf162*)&outl[off] = p;
                } else {
                    float2 m  = *(const float2*)&aux[off];
                    float2 rr = *(const float2*)&res[off];
                    float2 o;
                    o.x = rr.x + ((m.x > 0.5f) ? v0 : 0.f);
                    o.y = rr.y + ((m.y > 0.5f) ? v1 : 0.f);
                    *(float2*)&outf[off] = o;
                }
            }
        }
    }
}

// ------- sparse attention: HMMA scores, early-exit top-k, compacted PV -----
// (round-9 structure: 32 q-rows/block, double-buffered K; V now fp16)
#define SS_STR  1034
#define SS_OFF  20736
#define ATTN_SMEM (9216 + 73728 + 32*SS_STR*4)

__device__ __forceinline__ void issue_k(uint32_t sb, size_t bhoff, int kt, int buf, int tid) {
    #pragma unroll
    for (int i = 0; i < 4; ++i) {
        int lin = tid + (i << 9);
        int tile = lin >> 10, wit = lin & 1023;
        int r = wit >> 3, ch = wit & 7;
        const bf16* gsrc = (tile ? g_kl : g_kh) + bhoff + (size_t)(kt*128 + r)*64 + ch*8;
        CP_ASYNC16(sb + 9216 + buf*36864 + tile*18432 + r*144 + ch*16, gsrc);
    }
    CP_COMMIT();
}

__device__ __forceinline__ float dec(unsigned ub) {
    unsigned fb = ub ^ ((ub & 0x80000000u) ? 0x80000000u : 0xFFFFFFFFu);
    return __uint_as_float(fb);
}

__global__ void __launch_bounds__(512)
attn_kernel()
{
    extern __shared__ char smraw[];
    float* smf = (float*)smraw;
    uint32_t sb = s2u(smraw);

    int blk = blockIdx.x, bh = blk >> 5, n0 = (blk & 31) << 5;
    int tid = threadIdx.x, lane = tid & 31, w = tid >> 5;
    const size_t bhoff = (size_t)bh * 65536;

    {
        int tile = tid >> 8, wit = tid & 255, r = wit >> 3, ch = wit & 7;
        const bf16* gsrc = (tile ? g_ql : g_qh) + bhoff + (size_t)(n0 + r)*64 + ch*8;
        *(uint4*)(smraw + tile*4608 + r*144 + ch*16) = *(const uint4*)gsrc;
    }
    issue_k(sb, bhoff, 0, 0, tid);
    __syncthreads();

    const int wm = w & 1, wn = w >> 1;
    const int a_ro = lane & 15, a_ko = (lane >> 4) * 8;
    const int b_rp = ((lane >> 4) & 1) * 8 + (lane & 7);
    const int b_ko = ((lane >> 3) & 1) * 8;
    uint32_t qhi[4][4], qlo[4][4];
    #pragma unroll
    for (int ks = 0; ks < 4; ++ks) {
        uint32_t qa = sb + (wm*16 + a_ro)*144 + (ks*16 + a_ko)*2;
        ldsm4(qhi[ks], qa);
        ldsm4(qlo[ks], qa + 4608);
    }
    const int tr = lane >> 2, tc = (lane & 3) * 2;

    // ---- phase 1: scores via HMMA (double-buffered K) ----
    for (int kt = 0; kt < 8; ++kt) {
        CP_WAIT0();
        __syncthreads();
        if (kt < 7) issue_k(sb, bhoff, kt + 1, (kt + 1) & 1, tid);
        uint32_t kb = sb + 9216 + (kt & 1)*36864;
        float acc[2][4];
        #pragma unroll
        for (int nf = 0; nf < 2; ++nf)
            #pragma unroll
            for (int q = 0; q < 4; ++q) acc[nf][q] = 0.f;
        #pragma unroll
        for (int ks = 0; ks < 4; ++ks) {
            uint32_t bd = kb + (wn*16 + b_rp)*144 + (ks*16 + b_ko)*2;
            uint32_t bhi[4], blo[4];
            ldsm4(bhi, bd);
            ldsm4(blo, bd + 18432);
            mma16816(acc[0], qhi[ks], &bhi[0]);
            mma16816(acc[1], qhi[ks], &bhi[2]);
            mma16816(acc[0], qhi[ks], &blo[0]);
            mma16816(acc[1], qhi[ks], &blo[2]);
            mma16816(acc[0], qlo[ks], &bhi[0]);
            mma16816(acc[1], qlo[ks], &bhi[2]);
        }
        #pragma unroll
        for (int nf = 0; nf < 2; ++nf) {
            int key = kt*128 + wn*16 + nf*8 + tc;
            int row0 = wm*16 + tr;
            float2 o;
            o.x = acc[nf][0]*0.125f; o.y = acc[nf][1]*0.125f;
            *(float2*)&smf[SS_OFF + row0*SS_STR + key] = o;
            o.x = acc[nf][2]*0.125f; o.y = acc[nf][3]*0.125f;
            *(float2*)&smf[SS_OFF + (row0+8)*SS_STR + key] = o;
        }
    }
    __syncthreads();

    // ---- per-row: early-exit top-k threshold, softmax, compaction, PV ----
    int r0 = 2 * w;
    float o00=0, o01=0, o10=0, o11=0;
    const __half* Vb = g_v + bhoff;
    #pragma unroll 1
    for (int rr = 0; rr < 2; ++rr) {
        float* srow = &smf[SS_OFF + (r0 + rr) * SS_STR];
        unsigned key[32];
        float lmax = -3.4e38f;
        #pragma unroll
        for (int i = 0; i < 32; ++i) {
            float s = srow[lane + 32*i];
            lmax = fmaxf(lmax, s);
            unsigned ub = __float_as_uint(s);
            key[i] = ub ^ (((unsigned)((int)ub >> 31)) | 0x80000000u);
        }
        #pragma unroll
        for (int o = 16; o; o >>= 1) lmax = fmaxf(lmax, __shfl_xor_sync(~0u, lmax, o));

        unsigned T;
        {
            unsigned lo = 0u, hi = 0xFFFFFFFFu;
            while (lo < hi) {
                unsigned mid = lo + (unsigned)(((unsigned long long)(hi - lo) + 1ull) >> 1);
                unsigned c = 0;
                #pragma unroll
                for (int i = 0; i < 32; ++i) c += (key[i] >= mid) ? 1u : 0u;
                c = __reduce_add_sync(~0u, c);
                if (c == (unsigned)KSP) { lo = mid; break; }
                if (c > (unsigned)KSP) lo = mid; else hi = mid - 1u;
            }
            T = lo;
        }

        float lsum = 0.f;
        #pragma unroll
        for (int i = 0; i < 32; ++i) {
            if (key[i] >= T) lsum += __expf(dec(key[i]) - lmax);
        }
        #pragma unroll
        for (int o = 16; o; o >>= 1) lsum += __shfl_xor_sync(~0u, lsum, o);
        float inv = 1.f / lsum;

        uint2* lst = (uint2*)srow;
        int cnt = 0;
        #pragma unroll
        for (int i = 0; i < 32; ++i) {
            bool sel = key[i] >= T;
            unsigned mask = __ballot_sync(~0u, sel);
            if (sel) {
                int ofs = cnt + __popc(mask & ((1u << lane) - 1u));
                float p = __expf(dec(key[i]) - lmax) * inv;
                if (ofs < 128) {
                    uint2 e; e.x = __float_as_uint(p); e.y = (unsigned)(lane + 32*i);
                    lst[ofs] = e;
                }
            }
            cnt += __popc(mask);
        }
        if (cnt > 128) cnt = 128;
        __syncwarp();

        // sparse PV: one half2 LDG per entry (lane owns dims 2l, 2l+1)
        float a0 = 0.f, a1 = 0.f;
        #pragma unroll 4
        for (int j = 0; j < cnt; ++j) {
            uint2 e = lst[j];
            float p = __uint_as_float(e.x);
            __half2 hv = __ldg((const __half2*)(Vb + (size_t)e.y * 64) + lane);
            float2 v = __half22float2(hv);
            a0 = fmaf(p, v.x, a0);
            a1 = fmaf(p, v.y, a1);
        }
        if (rr == 0) { o00 = a0; o01 = a1; } else { o10 = a0; o11 = a1; }
    }

    // writeback: lane owns dims (2*lane, 2*lane+1)
    int bb = bh >> 4, hh = bh & 15;
    {
        size_t base0 = ((size_t)(bb*1024 + n0 + r0    )) * 1024 + hh*64 + lane*2;
        size_t base1 = ((size_t)(bb*1024 + n0 + r0 + 1)) * 1024 + hh*64 + lane*2;
        bf16 h0, l0, h1, l1;
        bfsplit(o00, h0, l0); bfsplit(o01, h1, l1);
        bf162 ph, pl; ph.x = h0; ph.y = h1; pl.x = l0; pl.y = l1;
        *(bf162*)&g_ath[base0] = ph; *(bf162*)&g_atl[base0] = pl;
        bfsplit(o10, h0, l0); bfsplit(o11, h1, l1);
        ph.x = h0; ph.y = h1; pl.x = l0; pl.y = l1;
        *(bf162*)&g_ath[base1] = ph; *(bf162*)&g_atl[base1] = pl;
    }
}

// ---------------- launch ----------------
extern "C" void kernel_launch(void* const* d_in, const int* in_sizes, int n_in,
                              void* d_out, int out_size)
{
    (void)in_sizes; (void)n_in; (void)out_size;
    const float* x     = (const float*)d_in[0];
    const float* ln1_w = (const float*)d_in[1];
    const float* ln1_b = (const float*)d_in[2];
    const float* qkv_w = (const float*)d_in[3];
    const float* qkv_b = (const float*)d_in[4];
    const float* out_w = (const float*)d_in[5];
    const float* out_b = (const float*)d_in[6];
    const float* ln2_w = (const float*)d_in[7];
    const float* ln2_b = (const float*)d_in[8];
    const float* w1    = (const float*)d_in[9];
    const float* b1    = (const float*)d_in[10];
    const float* w2    = (const float*)d_in[11];
    const float* b2    = (const float*)d_in[12];
    const float* mask1 = (const float*)d_in[13];
    const float* mask2 = (const float*)d_in[14];
    float* out = (float*)d_out;

    void *x1, *xnh, *xnl, *hnh, *hnl, *ath, *atl, *h1h, *h1l,
         *qwh, *qwl, *owh, *owl, *w1h, *w1l, *w2h, *w2l;
    cudaGetSymbolAddress(&x1, g_x1);
    cudaGetSymbolAddress(&xnh, g_xnh); cudaGetSymbolAddress(&xnl, g_xnl);
    cudaGetSymbolAddress(&hnh, g_hnh); cudaGetSymbolAddress(&hnl, g_hnl);
    cudaGetSymbolAddress(&ath, g_ath); cudaGetSymbolAddress(&atl, g_atl);
    cudaGetSymbolAddress(&h1h, g_h1h); cudaGetSymbolAddress(&h1l, g_h1l);
    cudaGetSymbolAddress(&qwh, g_qwh); cudaGetSymbolAddress(&qwl, g_qwl);
    cudaGetSymbolAddress(&owh, g_owh); cudaGetSymbolAddress(&owl, g_owl);
    cudaGetSymbolAddress(&w1h, g_w1h); cudaGetSymbolAddress(&w1l, g_w1l);
    cudaGetSymbolAddress(&w2h, g_w2h); cudaGetSymbolAddress(&w2l, g_w2l);

    cudaFuncSetAttribute(attn_kernel, cudaFuncAttributeMaxDynamicSharedMemorySize, ATTN_SMEM);
    cudaFuncSetAttribute(tc_gemm<0>, cudaFuncAttributeMaxDynamicSharedMemorySize, GSMEM);
    cudaFuncSetAttribute(tc_gemm<1>, cudaFuncAttributeMaxDynamicSharedMemorySize, GSMEM);
    cudaFuncSetAttribute(tc_gemm<2>, cudaFuncAttributeMaxDynamicSharedMemorySize, GSMEM);
    cudaFuncSetAttribute(tc_gemm<3>, cudaFuncAttributeMaxDynamicSharedMemorySize, GSMEM);

    // launch order: [0]cvt4 [1]ln1 [2]gemm0 [3]attn  -> ncu captures attn
    cvt4<<<12288, 256>>>(qkv_w, (bf16*)qwh, (bf16*)qwl, 786432,
                         out_w, (bf16*)owh, (bf16*)owl, 262144,
                         w1,    (bf16*)w1h, (bf16*)w1l, 1048576,
                         w2,    (bf16*)w2h, (bf16*)w2l, 1048576);

    ln_bf16<<<M_, 256>>>(x, ln1_w, ln1_b, (bf16*)xnh, (bf16*)xnl);

    tc_gemm<0><<<dim3(24, 64), 256, GSMEM>>>((bf16*)xnh, (bf16*)xnl,
        (bf16*)qwh, (bf16*)qwl, qkv_b, nullptr, nullptr, nullptr, nullptr, nullptr,
        3*C_, C_);

    attn_kernel<<<BH_*(N_/32), 512, ATTN_SMEM>>>();

    tc_gemm<1><<<dim3(8, 64), 256, GSMEM>>>((bf16*)ath, (bf16*)atl,
        (bf16*)owh, (bf16*)owl, out_b, nullptr, x, (float*)x1, nullptr, nullptr,
        C_, C_);

    ln_bf16<<<M_, 256>>>((float*)x1, ln2_w, ln2_b, (bf16*)hnh, (bf16*)hnl);

    tc_gemm<2><<<dim3(32, 64), 256, GSMEM>>>((bf16*)hnh, (bf16*)hnl,
        (bf16*)w1h, (bf16*)w1l, b1, mask1, nullptr, nullptr, (bf16*)h1h, (bf16*)h1l,
        FF_, C_);

    tc_gemm<3><<<dim3(8, 64), 256, GSMEM>>>((bf16*)h1h, (bf16*)h1l,
        (bf16*)w2h, (bf16*)w2l, b2, mask2, (float*)x1, out, nullptr, nullptr,
        C_, FF_);
}

// round 13
// speedup vs baseline: 1.1716x; 1.1387x over previous
#include <cuda_runtime.h>
#include <cuda_bf16.h>
#include <cuda_fp16.h>
#include <stdint.h>

#define B_   8
#define N_   1024
#define C_   1024
#define HD_  64
#define FF_  4096
#define BH_  128
#define M_   8192
#define KSP  102

typedef __nv_bfloat16 bf16;
typedef __nv_bfloat162 bf162;

// ---------------- scratch ----------------
__device__ __align__(256) __half g_v[(size_t)BH_*N_*HD_];
__device__ __align__(256) float g_x1[(size_t)M_*C_];
__device__ __align__(256) bf16 g_qh[(size_t)BH_*N_*HD_], g_ql[(size_t)BH_*N_*HD_];
__device__ __align__(256) bf16 g_kh[(size_t)BH_*N_*HD_], g_kl[(size_t)BH_*N_*HD_];
__device__ __align__(256) bf16 g_xnh[(size_t)M_*C_],  g_xnl[(size_t)M_*C_];
__device__ __align__(256) bf16 g_qwh[(size_t)3*C_*C_], g_qwl[(size_t)3*C_*C_];
__device__ __align__(256) __half g_hnh[(size_t)M_*C_],  g_hnl[(size_t)M_*C_];
__device__ __align__(256) __half g_ath[(size_t)M_*C_],  g_atl[(size_t)M_*C_];
__device__ __align__(256) __half g_h1h[(size_t)M_*FF_], g_h1l[(size_t)M_*FF_];
__device__ __align__(256) __half g_ow16[(size_t)C_*C_];
__device__ __align__(256) __half g_w116[(size_t)FF_*C_];
__device__ __align__(256) __half g_w216[(size_t)C_*FF_];

// ---------------- helpers ----------------
__device__ __forceinline__ uint32_t s2u(const void* p) {
    uint32_t a;
    asm("{ .reg .u64 t; cvta.to.shared.u64 t, %1; cvt.u32.u64 %0, t; }" : "=r"(a) : "l"(p));
    return a;
}
__device__ __forceinline__ void bfsplit(float v, bf16& h, bf16& l) {
    h = __float2bfloat16(v);
    l = __float2bfloat16(v - __bfloat162float(h));
}
__device__ __forceinline__ void h16split(float v, __half& h, __half& l) {
    h = __float2half_rn(v);
    l = __float2half_rn(v - __half2float(h));
}
__device__ __forceinline__ void ldsm4(uint32_t* r, uint32_t a) {
    asm volatile("ldmatrix.sync.aligned.m8n8.x4.shared.b16 {%0,%1,%2,%3}, [%4];"
        : "=r"(r[0]), "=r"(r[1]), "=r"(r[2]), "=r"(r[3]) : "r"(a));
}
__device__ __forceinline__ void mma16816(float* c, const uint32_t* a, const uint32_t* b) {
    asm volatile("mma.sync.aligned.m16n8k16.row.col.f32.bf16.bf16.f32 "
        "{%0,%1,%2,%3}, {%4,%5,%6,%7}, {%8,%9}, {%0,%1,%2,%3};"
        : "+f"(c[0]), "+f"(c[1]), "+f"(c[2]), "+f"(c[3])
        : "r"(a[0]), "r"(a[1]), "r"(a[2]), "r"(a[3]), "r"(b[0]), "r"(b[1]));
}
__device__ __forceinline__ void mma16816h(float* c, const uint32_t* a, const uint32_t* b) {
    asm volatile("mma.sync.aligned.m16n8k16.row.col.f32.f16.f16.f32 "
        "{%0,%1,%2,%3}, {%4,%5,%6,%7}, {%8,%9}, {%0,%1,%2,%3};"
        : "+f"(c[0]), "+f"(c[1]), "+f"(c[2]), "+f"(c[3])
        : "r"(a[0]), "r"(a[1]), "r"(a[2]), "r"(a[3]), "r"(b[0]), "r"(b[1]));
}
#define CP_ASYNC16(s, g) \
    asm volatile("cp.async.cg.shared.global [%0], [%1], 16;" :: "r"(s), "l"(g))
#define CP_COMMIT() asm volatile("cp.async.commit_group;" ::: "memory")
#define CP_WAIT0()  asm volatile("cp.async.wait_group 0;" ::: "memory")
#define CP_WAIT1()  asm volatile("cp.async.wait_group 1;" ::: "memory")

// ---------------- weight conversions ----------------
__global__ void __launch_bounds__(256)
cvt_qkv(const float* __restrict__ s, bf16* __restrict__ h, bf16* __restrict__ l)
{
    int i = blockIdx.x * 256 + threadIdx.x;   // 786432 float4s
    float4 v = ((const float4*)s)[i];
    bf16 a0,a1,a2,a3,b0,b1,b2,b3;
    bfsplit(v.x,a0,b0); bfsplit(v.y,a1,b1); bfsplit(v.z,a2,b2); bfsplit(v.w,a3,b3);
    bf162 p,q;
    p.x=a0;p.y=a1;q.x=a2;q.y=a3; ((bf162*)h)[i*2]=p; ((bf162*)h)[i*2+1]=q;
    p.x=b0;p.y=b1;q.x=b2;q.y=b3; ((bf162*)l)[i*2]=p; ((bf162*)l)[i*2+1]=q;
}

__global__ void __launch_bounds__(256)
cvt_w16(const float* __restrict__ s0, __half* __restrict__ d0, int n0,
        const float* __restrict__ s1, __half* __restrict__ d1, int n1,
        const float* __restrict__ s2, __half* __restrict__ d2, int n2)
{
    int i = blockIdx.x * 256 + threadIdx.x;
    const float* s; __half* d;
    if (i < n0) { s = s0; d = d0; }
    else if ((i -= n0) < n1) { s = s1; d = d1; }
    else { i -= n1; if (i >= n2) return; s = s2; d = d2; }
    float4 v = ((const float4*)s)[i];
    __half2 a = __floats2half2_rn(v.x, v.y);
    __half2 b = __floats2half2_rn(v.z, v.w);
    ((__half2*)d)[i*2] = a; ((__half2*)d)[i*2+1] = b;
}

// ---------------- LayerNorms ----------------
__global__ void __launch_bounds__(256)
ln_bf16(const float* __restrict__ x, const float* __restrict__ w,
        const float* __restrict__ b, bf16* __restrict__ yh, bf16* __restrict__ yl)
{
    __shared__ float red[16];
    int row = blockIdx.x, t = threadIdx.x;
    float4 v = ((const float4*)(x + (size_t)row * 1024))[t];
    float s  = v.x + v.y + v.z + v.w;
    float ss = v.x*v.x + v.y*v.y + v.z*v.z + v.w*v.w;
    #pragma unroll
    for (int o = 16; o; o >>= 1) {
        s  += __shfl_xor_sync(~0u, s, o);
        ss += __shfl_xor_sync(~0u, ss, o);
    }
    if ((t & 31) == 0) { red[t>>5] = s; red[(t>>5)+8] = ss; }
    __syncthreads();
    if (t == 0) {
        float ts=0.f, tss=0.f;
        #pragma unroll
        for (int i = 0; i < 8; ++i) { ts += red[i]; tss += red[i+8]; }
        float mu = ts * (1.f/1024.f);
        red[0] = mu; red[1] = rsqrtf(tss*(1.f/1024.f) - mu*mu + 1e-5f);
    }
    __syncthreads();
    float mu = red[0], rs = red[1];
    float4 wv = ((const float4*)w)[t];
    float4 bv = ((const float4*)b)[t];
    float o0 = (v.x-mu)*rs*wv.x + bv.x, o1 = (v.y-mu)*rs*wv.y + bv.y;
    float o2 = (v.z-mu)*rs*wv.z + bv.z, o3 = (v.w-mu)*rs*wv.w + bv.w;
    bf16 h0,h1,h2,h3,l0,l1,l2,l3;
    bfsplit(o0,h0,l0); bfsplit(o1,h1,l1); bfsplit(o2,h2,l2); bfsplit(o3,h3,l3);
    size_t oi = ((size_t)row*1024 + t*4) >> 1;
    bf162 pa, pb;
    pa.x=h0;pa.y=h1;pb.x=h2;pb.y=h3; ((bf162*)yh)[oi]=pa; ((bf162*)yh)[oi+1]=pb;
    pa.x=l0;pa.y=l1;pb.x=l2;pb.y=l3; ((bf162*)yl)[oi]=pa; ((bf162*)yl)[oi+1]=pb;
}

__global__ void __launch_bounds__(256)
ln_f16(const float* __restrict__ x, const float* __restrict__ w,
       const float* __restrict__ b, __half* __restrict__ yh, __half* __restrict__ yl)
{
    __shared__ float red[16];
    int row = blockIdx.x, t = threadIdx.x;
    float4 v = ((const float4*)(x + (size_t)row * 1024))[t];
    float s  = v.x + v.y + v.z + v.w;
    float ss = v.x*v.x + v.y*v.y + v.z*v.z + v.w*v.w;
    #pragma unroll
    for (int o = 16; o; o >>= 1) {
        s  += __shfl_xor_sync(~0u, s, o);
        ss += __shfl_xor_sync(~0u, ss, o);
    }
    if ((t & 31) == 0) { red[t>>5] = s; red[(t>>5)+8] = ss; }
    __syncthreads();
    if (t == 0) {
        float ts=0.f, tss=0.f;
        #pragma unroll
        for (int i = 0; i < 8; ++i) { ts += red[i]; tss += red[i+8]; }
        float mu = ts * (1.f/1024.f);
        red[0] = mu; red[1] = rsqrtf(tss*(1.f/1024.f) - mu*mu + 1e-5f);
    }
    __syncthreads();
    float mu = red[0], rs = red[1];
    float4 wv = ((const float4*)w)[t];
    float4 bv = ((const float4*)b)[t];
    float o0 = (v.x-mu)*rs*wv.x + bv.x, o1 = (v.y-mu)*rs*wv.y + bv.y;
    float o2 = (v.z-mu)*rs*wv.z + bv.z, o3 = (v.w-mu)*rs*wv.w + bv.w;
    __half h0,h1,h2,h3,l0,l1,l2,l3;
    h16split(o0,h0,l0); h16split(o1,h1,l1); h16split(o2,h2,l2); h16split(o3,h3,l3);
    size_t oi = ((size_t)row*1024 + t*4) >> 1;
    __half2 pa, pb;
    pa.x=h0;pa.y=h1;pb.x=h2;pb.y=h3; ((__half2*)yh)[oi]=pa; ((__half2*)yh)[oi+1]=pb;
    pa.x=l0;pa.y=l1;pb.x=l2;pb.y=l3; ((__half2*)yl)[oi]=pa; ((__half2*)yl)[oi+1]=pb;
}

// ---- bf16x3 GEMM (QKV only): 128x128 tile, 2-stage, 2 CTAs/SM ----
#define ATILE_B  10240
#define STAGE_B  40960
#define GSMEM    (2*STAGE_B)

__device__ __forceinline__ void issue_stage(
    const bf16* __restrict__ Ah, const bf16* __restrict__ Al,
    const bf16* __restrict__ Bh, const bf16* __restrict__ Bl,
    uint32_t sbase, int bm, int bn, int ko, int K, int tid)
{
    #pragma unroll
    for (int i = 0; i < 8; ++i) {
        int lin = tid + (i << 8);
        int tile = lin >> 9;
        int wit = lin & 511;
        int r = wit >> 2, ch = wit & 3;
        const bf16* gp;
        if      (tile == 0) gp = Ah + (size_t)(bm + r) * K + ko + ch*8;
        else if (tile == 1) gp = Al + (size_t)(bm + r) * K + ko + ch*8;
        else if (tile == 2) gp = Bh + (size_t)(bn + r) * K + ko + ch*8;
        else                gp = Bl + (size_t)(bn + r) * K + ko + ch*8;
        CP_ASYNC16(sbase + tile*ATILE_B + r*80 + ch*16, gp);
    }
    CP_COMMIT();
}

__global__ void __launch_bounds__(256, 2)
tc_gemm_qkv(const bf16* __restrict__ Ah, const bf16* __restrict__ Al,
            const bf16* __restrict__ Bh, const bf16* __restrict__ Bl,
            const float* __restrict__ bias, int N, int K)
{
    extern __shared__ char smem[];
    uint32_t sb = s2u(smem);
    const int tid = threadIdx.x, lane = tid & 31, wid = tid >> 5;
    const int wm = wid & 3, wn = wid >> 2;
    const int bm = blockIdx.y << 7, bn = blockIdx.x << 7;

    float acc[2][8][4];
    #pragma unroll
    for (int i = 0; i < 2; ++i)
        #pragma unroll
        for (int j = 0; j < 8; ++j)
            #pragma unroll
            for (int q = 0; q < 4; ++q) acc[i][j][q] = 0.f;

    const int ktn = K >> 5;
    issue_stage(Ah, Al, Bh, Bl, sb, bm, bn, 0, K, tid);

    const int a_ro = (lane & 15);
    const int a_ko = (lane >> 4) * 8;
    const int b_rp = ((lane >> 4) & 1) * 8 + (lane & 7);
    const int b_ko = ((lane >> 3) & 1) * 8;

    for (int kt = 0; kt < ktn; ++kt) {
        CP_WAIT0();
        __syncthreads();
        if (kt + 1 < ktn)
            issue_stage(Ah, Al, Bh, Bl, sb + ((kt + 1) & 1) * STAGE_B,
                        bm, bn, (kt + 1) * 32, K, tid);
        uint32_t st = sb + (kt & 1) * STAGE_B;
        #pragma unroll
        for (int ks = 0; ks < 2; ++ks) {
            uint32_t ahi[2][4], alo[2][4], bhi[4][4], blo[4][4];
            #pragma unroll
            for (int mf = 0; mf < 2; ++mf)
                ldsm4(ahi[mf], st + (wm*32 + mf*16 + a_ro)*80 + (ks*16 + a_ko)*2);
            #pragma unroll
            for (int np = 0; np < 4; ++np)
                ldsm4(bhi[np], st + 2*ATILE_B + (wn*64 + np*16 + b_rp)*80 + (ks*16 + b_ko)*2);
            #pragma unroll
            for (int np = 0; np < 4; ++np)
                #pragma unroll
                for (int mf = 0; mf < 2; ++mf) {
                    mma16816(acc[mf][np*2  ], ahi[mf], &bhi[np][0]);
                    mma16816(acc[mf][np*2+1], ahi[mf], &bhi[np][2]);
                }
            #pragma unroll
            for (int np = 0; np < 4; ++np)
                ldsm4(blo[np], st + 3*ATILE_B + (wn*64 + np*16 + b_rp)*80 + (ks*16 + b_ko)*2);
            #pragma unroll
            for (int np = 0; np < 4; ++np)
                #pragma unroll
                for (int mf = 0; mf < 2; ++mf) {
                    mma16816(acc[mf][np*2  ], ahi[mf], &blo[np][0]);
                    mma16816(acc[mf][np*2+1], ahi[mf], &blo[np][2]);
                }
            #pragma unroll
            for (int mf = 0; mf < 2; ++mf)
                ldsm4(alo[mf], st + ATILE_B + (wm*32 + mf*16 + a_ro)*80 + (ks*16 + a_ko)*2);
            #pragma unroll
            for (int np = 0; np < 4; ++np)
                #pragma unroll
                for (int mf = 0; mf < 2; ++mf) {
                    mma16816(acc[mf][np*2  ], alo[mf], &bhi[np][0]);
                    mma16816(acc[mf][np*2+1], alo[mf], &bhi[np][2]);
                }
        }
    }

    const int tr = lane >> 2;
    const int tc = (lane & 3) * 2;
    #pragma unroll
    for (int mf = 0; mf < 2; ++mf) {
        #pragma unroll
        for (int nf = 0; nf < 8; ++nf) {
            int gj = bn + wn*64 + nf*8 + tc;
            float2 b2 = *(const float2*)&bias[gj];
            #pragma unroll
            for (int h = 0; h < 2; ++h) {
                int gi = bm + wm*32 + mf*16 + tr + h*8;
                float v0 = acc[mf][nf][h*2]   + b2.x;
                float v1 = acc[mf][nf][h*2+1] + b2.y;
                int wh = gj >> 10, hh = (gj >> 6) & 15, d = gj & 63;
                int bb = gi >> 10, nn = gi & 1023;
                size_t idx = (((size_t)(bb*16 + hh))*1024 + nn)*64 + d;
                if (wh == 2) {
                    *(__half2*)&g_v[idx] = __floats2half2_rn(v0, v1);
                } else {
                    bf16 h0,l0,h1,l1;
                    bfsplit(v0,h0,l0); bfsplit(v1,h1,l1);
                    bf162 ph, pl; ph.x=h0; ph.y=h1; pl.x=l0; pl.y=l1;
                    if (wh == 0) { *(bf162*)&g_qh[idx]=ph; *(bf162*)&g_ql[idx]=pl; }
                    else         { *(bf162*)&g_kh[idx]=ph; *(bf162*)&g_kl[idx]=pl; }
                }
            }
        }
    }
}

// ---- fp16x2 GEMM: A split (hi/lo), B single; 3-stage, 2 CTAs/SM ----
// stage: Ah 10KB | Al 10KB | B 10KB = 30720 B
#define STAGE_H  30720
#define GSMEM_H  (3*STAGE_H)

__device__ __forceinline__ void issue_stage_h(
    const __half* __restrict__ Ah, const __half* __restrict__ Al,
    const __half* __restrict__ Bs,
    uint32_t sbase, int bm, int bn, int ko, int K, int tid)
{
    #pragma unroll
    for (int i = 0; i < 6; ++i) {
        int lin = tid + (i << 8);          // 0..1535
        int tile = lin >> 9;
        int wit = lin & 511;
        int r = wit >> 2, ch = wit & 3;
        const __half* gp;
        if      (tile == 0) gp = Ah + (size_t)(bm + r) * K + ko + ch*8;
        else if (tile == 1) gp = Al + (size_t)(bm + r) * K + ko + ch*8;
        else                gp = Bs + (size_t)(bn + r) * K + ko + ch*8;
        CP_ASYNC16(sbase + tile*ATILE_B + r*80 + ch*16, gp);
    }
    CP_COMMIT();
}

// EPI 1: +bias+res->outf | 2: h16split(relu(acc+b)*(m>.5))->outh/l | 3: res+(acc+b)*m->outf
template<int EPI>
__global__ void __launch_bounds__(256, 2)
tc_gemm16(const __half* __restrict__ Ah, const __half* __restrict__ Al,
          const __half* __restrict__ Bs,
          const float* __restrict__ bias, const float* __restrict__ aux,
          const float* __restrict__ res, float* __restrict__ outf,
          __half* __restrict__ outh, __half* __restrict__ outl, int N, int K)
{
    extern __shared__ char smem[];
    uint32_t sb = s2u(smem);
    const int tid = threadIdx.x, lane = tid & 31, wid = tid >> 5;
    const int wm = wid & 3, wn = wid >> 2;
    const int bm = blockIdx.y << 7, bn = blockIdx.x << 7;

    float acc[2][8][4];
    #pragma unroll
    for (int i = 0; i < 2; ++i)
        #pragma unroll
        for (int j = 0; j < 8; ++j)
            #pragma unroll
            for (int q = 0; q < 4; ++q) acc[i][j][q] = 0.f;

    const int ktn = K >> 5;
    issue_stage_h(Ah, Al, Bs, sb, bm, bn, 0, K, tid);
    if (ktn > 1) issue_stage_h(Ah, Al, Bs, sb + STAGE_H, bm, bn, 32, K, tid);

    const int a_ro = (lane & 15);
    const int a_ko = (lane >> 4) * 8;
    const int b_rp = ((lane >> 4) & 1) * 8 + (lane & 7);
    const int b_ko = ((lane >> 3) & 1) * 8;

    for (int kt = 0; kt < ktn; ++kt) {
        if (kt + 1 < ktn) CP_WAIT1(); else CP_WAIT0();
        __syncthreads();
        if (kt + 2 < ktn)
            issue_stage_h(Ah, Al, Bs, sb + ((kt + 2) % 3) * STAGE_H,
                          bm, bn, (kt + 2) * 32, K, tid);
        uint32_t st = sb + (kt % 3) * STAGE_H;
        #pragma unroll
        for (int ks = 0; ks < 2; ++ks) {
            uint32_t ahi[2][4], alo[2][4], bfr[4][4];
            #pragma unroll
            for (int mf = 0; mf < 2; ++mf) {
                uint32_t ad = st + (wm*32 + mf*16 + a_ro)*80 + (ks*16 + a_ko)*2;
                ldsm4(ahi[mf], ad);
                ldsm4(alo[mf], ad + ATILE_B);
            }
            #pragma unroll
            for (int np = 0; np < 4; ++np)
                ldsm4(bfr[np], st + 2*ATILE_B + (wn*64 + np*16 + b_rp)*80 + (ks*16 + b_ko)*2);
            #pragma unroll
            for (int np = 0; np < 4; ++np)
                #pragma unroll
                for (int mf = 0; mf < 2; ++mf) {
                    mma16816h(acc[mf][np*2  ], ahi[mf], &bfr[np][0]);
                    mma16816h(acc[mf][np*2+1], ahi[mf], &bfr[np][2]);
                }
            #pragma unroll
            for (int np = 0; np < 4; ++np)
                #pragma unroll
                for (int mf = 0; mf < 2; ++mf) {
                    mma16816h(acc[mf][np*2  ], alo[mf], &bfr[np][0]);
                    mma16816h(acc[mf][np*2+1], alo[mf], &bfr[np][2]);
                }
        }
    }

    const int tr = lane >> 2;
    const int tc = (lane & 3) * 2;
    #pragma unroll
    for (int mf = 0; mf < 2; ++mf) {
        #pragma unroll
        for (int nf = 0; nf < 8; ++nf) {
            int gj = bn + wn*64 + nf*8 + tc;
            float2 b2 = *(const float2*)&bias[gj];
            #pragma unroll
            for (int h = 0; h < 2; ++h) {
                int gi = bm + wm*32 + mf*16 + tr + h*8;
                float v0 = acc[mf][nf][h*2]   + b2.x;
                float v1 = acc[mf][nf][h*2+1] + b2.y;
                size_t off = (size_t)gi * N + gj;
                if (EPI == 1) {
                    float2 rr = *(const float2*)&res[off];
                    float2 o; o.x = v0 + rr.x; o.y = v1 + rr.y;
                    *(float2*)&outf[off] = o;
                } else if (EPI == 2) {
                    float2 m = *(const float2*)&aux[off];
                    v0 = (m.x > 0.5f) ? fmaxf(v0, 0.f) : 0.f;
                    v1 = (m.y > 0.5f) ? fmaxf(v1, 0.f) : 0.f;
                    __half h0,l0,h1,l1;
                    h16split(v0,h0,l0); h16split(v1,h1,l1);
                    __half2 p; p.x=h0; p.y=h1; *(__half2*)&outh[off] = p;
                    p.x=l0; p.y=l1;            *(__half2*)&outl[off] = p;
                } else {
                    float2 m  = *(const float2*)&aux[off];
                    float2 rr = *(const float2*)&res[off];
                    float2 o;
                    o.x = rr.x + ((m.x > 0.5f) ? v0 : 0.f);
                    o.y = rr.y + ((m.y > 0.5f) ? v1 : 0.f);
                    *(float2*)&outf[off] = o;
                }
            }
        }
    }
}

// ------- sparse attention (round-9 structure; fp16 V; fp16 output) --------
#define SS_STR  1034
#define SS_OFF  20736
#define ATTN_SMEM (9216 + 73728 + 32*SS_STR*4)

__device__ __forceinline__ void issue_k(uint32_t sb, size_t bhoff, int kt, int buf, int tid) {
    #pragma unroll
    for (int i = 0; i < 4; ++i) {
        int lin = tid + (i << 9);
        int tile = lin >> 10, wit = lin & 1023;
        int r = wit >> 3, ch = wit & 7;
        const bf16* gsrc = (tile ? g_kl : g_kh) + bhoff + (size_t)(kt*128 + r)*64 + ch*8;
        CP_ASYNC16(sb + 9216 + buf*36864 + tile*18432 + r*144 + ch*16, gsrc);
    }
    CP_COMMIT();
}

__device__ __forceinline__ float dec(unsigned ub) {
    unsigned fb = ub ^ ((ub & 0x80000000u) ? 0x80000000u : 0xFFFFFFFFu);
    return __uint_as_float(fb);
}

__global__ void __launch_bounds__(512)
attn_kernel()
{
    extern __shared__ char smraw[];
    float* smf = (float*)smraw;
    uint32_t sb = s2u(smraw);

    int blk = blockIdx.x, bh = blk >> 5, n0 = (blk & 31) << 5;
    int tid = threadIdx.x, lane = tid & 31, w = tid >> 5;
    const size_t bhoff = (size_t)bh * 65536;

    {
        int tile = tid >> 8, wit = tid & 255, r = wit >> 3, ch = wit & 7;
        const bf16* gsrc = (tile ? g_ql : g_qh) + bhoff + (size_t)(n0 + r)*64 + ch*8;
        *(uint4*)(smraw + tile*4608 + r*144 + ch*16) = *(const uint4*)gsrc;
    }
    issue_k(sb, bhoff, 0, 0, tid);
    __syncthreads();

    const int wm = w & 1, wn = w >> 1;
    const int a_ro = lane & 15, a_ko = (lane >> 4) * 8;
    const int b_rp = ((lane >> 4) & 1) * 8 + (lane & 7);
    const int b_ko = ((lane >> 3) & 1) * 8;
    uint32_t qhi[4][4], qlo[4][4];
    #pragma unroll
    for (int ks = 0; ks < 4; ++ks) {
        uint32_t qa = sb + (wm*16 + a_ro)*144 + (ks*16 + a_ko)*2;
        ldsm4(qhi[ks], qa);
        ldsm4(qlo[ks], qa + 4608);
    }
    const int tr = lane >> 2, tc = (lane & 3) * 2;

    for (int kt = 0; kt < 8; ++kt) {
        CP_WAIT0();
        __syncthreads();
        if (kt < 7) issue_k(sb, bhoff, kt + 1, (kt + 1) & 1, tid);
        uint32_t kb = sb + 9216 + (kt & 1)*36864;
        float acc[2][4];
        #pragma unroll
        for (int nf = 0; nf < 2; ++nf)
            #pragma unroll
            for (int q = 0; q < 4; ++q) acc[nf][q] = 0.f;
        #pragma unroll
        for (int ks = 0; ks < 4; ++ks) {
            uint32_t bd = kb + (wn*16 + b_rp)*144 + (ks*16 + b_ko)*2;
            uint32_t bhi[4], blo[4];
            ldsm4(bhi, bd);
            ldsm4(blo, bd + 18432);
            mma16816(acc[0], qhi[ks], &bhi[0]);
            mma16816(acc[1], qhi[ks], &bhi[2]);
            mma16816(acc[0], qhi[ks], &blo[0]);
            mma16816(acc[1], qhi[ks], &blo[2]);
            mma16816(acc[0], qlo[ks], &bhi[0]);
            mma16816(acc[1], qlo[ks], &bhi[2]);
        }
        #pragma unroll
        for (int nf = 0; nf < 2; ++nf) {
            int key = kt*128 + wn*16 + nf*8 + tc;
            int row0 = wm*16 + tr;
            float2 o;
            o.x = acc[nf][0]*0.125f; o.y = acc[nf][1]*0.125f;
            *(float2*)&smf[SS_OFF + row0*SS_STR + key] = o;
            o.x = acc[nf][2]*0.125f; o.y = acc[nf][3]*0.125f;
            *(float2*)&smf[SS_OFF + (row0+8)*SS_STR + key] = o;
        }
    }
    __syncthreads();

    int r0 = 2 * w;
    float o00=0, o01=0, o10=0, o11=0;
    const __half* Vb = g_v + bhoff;
    #pragma unroll 1
    for (int rr = 0; rr < 2; ++rr) {
        float* srow = &smf[SS_OFF + (r0 + rr) * SS_STR];
        unsigned key[32];
        float lmax = -3.4e38f;
        #pragma unroll
        for (int i = 0; i < 32; ++i) {
            float s = srow[lane + 32*i];
            lmax = fmaxf(lmax, s);
            unsigned ub = __float_as_uint(s);
            key[i] = ub ^ (((unsigned)((int)ub >> 31)) | 0x80000000u);
        }
        #pragma unroll
        for (int o = 16; o; o >>= 1) lmax = fmaxf(lmax, __shfl_xor_sync(~0u, lmax, o));

        unsigned T;
        {
            unsigned lo = 0u, hi = 0xFFFFFFFFu;
            while (lo < hi) {
                unsigned mid = lo + (unsigned)(((unsigned long long)(hi - lo) + 1ull) >> 1);
                unsigned c = 0;
                #pragma unroll
                for (int i = 0; i < 32; ++i) c += (key[i] >= mid) ? 1u : 0u;
                c = __reduce_add_sync(~0u, c);
                if (c == (unsigned)KSP) { lo = mid; break; }
                if (c > (unsigned)KSP) lo = mid; else hi = mid - 1u;
            }
            T = lo;
        }

        float lsum = 0.f;
        #pragma unroll
        for (int i = 0; i < 32; ++i) {
            if (key[i] >= T) lsum += __expf(dec(key[i]) - lmax);
        }
        #pragma unroll
        for (int o = 16; o; o >>= 1) lsum += __shfl_xor_sync(~0u, lsum, o);
        float inv = 1.f / lsum;

        uint2* lst = (uint2*)srow;
        int cnt = 0;
        #pragma unroll
        for (int i = 0; i < 32; ++i) {
            bool sel = key[i] >= T;
            unsigned mask = __ballot_sync(~0u, sel);
            if (sel) {
                int ofs = cnt + __popc(mask & ((1u << lane) - 1u));
                float p = __expf(dec(key[i]) - lmax) * inv;
                if (ofs < 128) {
                    uint2 e; e.x = __float_as_uint(p); e.y = (unsigned)(lane + 32*i);
                    lst[ofs] = e;
                }
            }
            cnt += __popc(mask);
        }
        if (cnt > 128) cnt = 128;
        __syncwarp();

        float a0 = 0.f, a1 = 0.f;
        #pragma unroll 4
        for (int j = 0; j < cnt; ++j) {
            uint2 e = lst[j];
            float p = __uint_as_float(e.x);
            __half2 hv = __ldg((const __half2*)(Vb + (size_t)e.y * 64) + lane);
            float2 v = __half22float2(hv);
            a0 = fmaf(p, v.x, a0);
            a1 = fmaf(p, v.y, a1);
        }
        if (rr == 0) { o00 = a0; o01 = a1; } else { o10 = a0; o11 = a1; }
    }

    // writeback fp16 hi/lo: lane owns dims (2*lane, 2*lane+1)
    int bb = bh >> 4, hh = bh & 15;
    {
        size_t base0 = ((size_t)(bb*1024 + n0 + r0    )) * 1024 + hh*64 + lane*2;
        size_t base1 = ((size_t)(bb*1024 + n0 + r0 + 1)) * 1024 + hh*64 + lane*2;
        __half h0, l0, h1, l1;
        h16split(o00, h0, l0); h16split(o01, h1, l1);
        __half2 ph, pl; ph.x = h0; ph.y = h1; pl.x = l0; pl.y = l1;
        *(__half2*)&g_ath[base0] = ph; *(__half2*)&g_atl[base0] = pl;
        h16split(o10, h0, l0); h16split(o11, h1, l1);
        ph.x = h0; ph.y = h1; pl.x = l0; pl.y = l1;
        *(__half2*)&g_ath[base1] = ph; *(__half2*)&g_atl[base1] = pl;
    }
}

// ---------------- launch ----------------
extern "C" void kernel_launch(void* const* d_in, const int* in_sizes, int n_in,
                              void* d_out, int out_size)
{
    (void)in_sizes; (void)n_in; (void)out_size;
    const float* x     = (const float*)d_in[0];
    const float* ln1_w = (const float*)d_in[1];
    const float* ln1_b = (const float*)d_in[2];
    const float* qkv_w = (const float*)d_in[3];
    const float* qkv_b = (const float*)d_in[4];
    const float* out_w = (const float*)d_in[5];
    const float* out_b = (const float*)d_in[6];
    const float* ln2_w = (const float*)d_in[7];
    const float* ln2_b = (const float*)d_in[8];
    const float* w1    = (const float*)d_in[9];
    const float* b1    = (const float*)d_in[10];
    const float* w2    = (const float*)d_in[11];
    const float* b2    = (const float*)d_in[12];
    const float* mask1 = (const float*)d_in[13];
    const float* mask2 = (const float*)d_in[14];
    float* out = (float*)d_out;

    void *x1, *xnh, *xnl, *hnh, *hnl, *ath, *atl, *h1h, *h1l,
         *qwh, *qwl, *ow16, *w116, *w216;
    cudaGetSymbolAddress(&x1, g_x1);
    cudaGetSymbolAddress(&xnh, g_xnh); cudaGetSymbolAddress(&xnl, g_xnl);
    cudaGetSymbolAddress(&hnh, g_hnh); cudaGetSymbolAddress(&hnl, g_hnl);
    cudaGetSymbolAddress(&ath, g_ath); cudaGetSymbolAddress(&atl, g_atl);
    cudaGetSymbolAddress(&h1h, g_h1h); cudaGetSymbolAddress(&h1l, g_h1l);
    cudaGetSymbolAddress(&qwh, g_qwh); cudaGetSymbolAddress(&qwl, g_qwl);
    cudaGetSymbolAddress(&ow16, g_ow16);
    cudaGetSymbolAddress(&w116, g_w116);
    cudaGetSymbolAddress(&w216, g_w216);

    cudaFuncSetAttribute(attn_kernel, cudaFuncAttributeMaxDynamicSharedMemorySize, ATTN_SMEM);
    cudaFuncSetAttribute(tc_gemm_qkv, cudaFuncAttributeMaxDynamicSharedMemorySize, GSMEM);
    cudaFuncSetAttribute(tc_gemm16<1>, cudaFuncAttributeMaxDynamicSharedMemorySize, GSMEM_H);
    cudaFuncSetAttribute(tc_gemm16<2>, cudaFuncAttributeMaxDynamicSharedMemorySize, GSMEM_H);
    cudaFuncSetAttribute(tc_gemm16<3>, cudaFuncAttributeMaxDynamicSharedMemorySize, GSMEM_H);

    // order: [0]cvt_qkv [1]cvt_w16 [2]ln1 [3]gemm0  -> ncu captures gemm0
    cvt_qkv<<<3072, 256>>>(qkv_w, (bf16*)qwh, (bf16*)qwl);
    cvt_w16<<<9216, 256>>>(out_w, (__half*)ow16, 262144,
                           w1,    (__half*)w116, 1048576,
                           w2,    (__half*)w216, 1048576);

    ln_bf16<<<M_, 256>>>(x, ln1_w, ln1_b, (bf16*)xnh, (bf16*)xnl);

    tc_gemm_qkv<<<dim3(24, 64), 256, GSMEM>>>((bf16*)xnh, (bf16*)xnl,
        (bf16*)qwh, (bf16*)qwl, qkv_b, 3*C_, C_);

    attn_kernel<<<BH_*(N_/32), 512, ATTN_SMEM>>>();

    tc_gemm16<1><<<dim3(8, 64), 256, GSMEM_H>>>((__half*)ath, (__half*)atl,
        (__half*)ow16, out_b, nullptr, x, (float*)x1, nullptr, nullptr, C_, C_);

    ln_f16<<<M_, 256>>>((float*)x1, ln2_w, ln2_b, (__half*)hnh, (__half*)hnl);

    tc_gemm16<2><<<dim3(32, 64), 256, GSMEM_H>>>((__half*)hnh, (__half*)hnl,
        (__half*)w116, b1, mask1, nullptr, nullptr, (__half*)h1h, (__half*)h1l, FF_, C_);

    tc_gemm16<3><<<dim3(8, 64), 256, GSMEM_H>>>((__half*)h1h, (__half*)h1l,
        (__half*)w216, b2, mask2, (float*)x1, out, nullptr, nullptr, C_, FF_);
}

// round 14
// speedup vs baseline: 1.2821x; 1.0943x over previous
#include <cuda_runtime.h>
#include <cuda_fp16.h>
#include <stdint.h>

#define B_   8
#define N_   1024
#define C_   1024
#define HD_  64
#define FF_  4096
#define BH_  128
#define M_   8192
#define KSP  102

// ---------------- scratch ----------------
__device__ __align__(256) __half g_v[(size_t)BH_*N_*HD_];
__device__ __align__(256) float g_x1[(size_t)M_*C_];
__device__ __align__(256) __half g_qh[(size_t)BH_*N_*HD_], g_ql[(size_t)BH_*N_*HD_];
__device__ __align__(256) __half g_k16[(size_t)BH_*N_*HD_];
__device__ __align__(256) __half g_xnh[(size_t)M_*C_],  g_xnl[(size_t)M_*C_];
__device__ __align__(256) __half g_hnh[(size_t)M_*C_],  g_hnl[(size_t)M_*C_];
__device__ __align__(256) __half g_ath[(size_t)M_*C_],  g_atl[(size_t)M_*C_];
__device__ __align__(256) __half g_h1h[(size_t)M_*FF_], g_h1l[(size_t)M_*FF_];
__device__ __align__(256) __half g_qw16[(size_t)3*C_*C_];
__device__ __align__(256) __half g_ow16[(size_t)C_*C_];
__device__ __align__(256) __half g_w116[(size_t)FF_*C_];
__device__ __align__(256) __half g_w216[(size_t)C_*FF_];

// ---------------- helpers ----------------
__device__ __forceinline__ uint32_t s2u(const void* p) {
    uint32_t a;
    asm("{ .reg .u64 t; cvta.to.shared.u64 t, %1; cvt.u32.u64 %0, t; }" : "=r"(a) : "l"(p));
    return a;
}
__device__ __forceinline__ void h16split(float v, __half& h, __half& l) {
    h = __float2half_rn(v);
    l = __float2half_rn(v - __half2float(h));
}
__device__ __forceinline__ void ldsm4(uint32_t* r, uint32_t a) {
    asm volatile("ldmatrix.sync.aligned.m8n8.x4.shared.b16 {%0,%1,%2,%3}, [%4];"
        : "=r"(r[0]), "=r"(r[1]), "=r"(r[2]), "=r"(r[3]) : "r"(a));
}
__device__ __forceinline__ void mma16816h(float* c, const uint32_t* a, const uint32_t* b) {
    asm volatile("mma.sync.aligned.m16n8k16.row.col.f32.f16.f16.f32 "
        "{%0,%1,%2,%3}, {%4,%5,%6,%7}, {%8,%9}, {%0,%1,%2,%3};"
        : "+f"(c[0]), "+f"(c[1]), "+f"(c[2]), "+f"(c[3])
        : "r"(a[0]), "r"(a[1]), "r"(a[2]), "r"(a[3]), "r"(b[0]), "r"(b[1]));
}
#define CP_ASYNC16(s, g) \
    asm volatile("cp.async.cg.shared.global [%0], [%1], 16;" :: "r"(s), "l"(g))
#define CP_COMMIT() asm volatile("cp.async.commit_group;" ::: "memory")
#define CP_WAIT0()  asm volatile("cp.async.wait_group 0;" ::: "memory")
#define CP_WAIT1()  asm volatile("cp.async.wait_group 1;" ::: "memory")

// ---------------- weight conversion: all weights -> fp16 ----------------
__global__ void __launch_bounds__(256)
cvt_w16(const float* __restrict__ s0, __half* __restrict__ d0, int n0,
        const float* __restrict__ s1, __half* __restrict__ d1, int n1,
        const float* __restrict__ s2, __half* __restrict__ d2, int n2,
        const float* __restrict__ s3, __half* __restrict__ d3, int n3)
{
    int i = blockIdx.x * 256 + threadIdx.x;
    const float* s; __half* d;
    if (i < n0) { s = s0; d = d0; }
    else if ((i -= n0) < n1) { s = s1; d = d1; }
    else if ((i -= n1) < n2) { s = s2; d = d2; }
    else { i -= n2; if (i >= n3) return; s = s3; d = d3; }
    float4 v = ((const float4*)s)[i];
    ((__half2*)d)[i*2]   = __floats2half2_rn(v.x, v.y);
    ((__half2*)d)[i*2+1] = __floats2half2_rn(v.z, v.w);
}

// ---------------- LayerNorm -> fp16 hi/lo ----------------
__global__ void __launch_bounds__(256)
ln_f16(const float* __restrict__ x, const float* __restrict__ w,
       const float* __restrict__ b, __half* __restrict__ yh, __half* __restrict__ yl)
{
    __shared__ float red[16];
    int row = blockIdx.x, t = threadIdx.x;
    float4 v = ((const float4*)(x + (size_t)row * 1024))[t];
    float s  = v.x + v.y + v.z + v.w;
    float ss = v.x*v.x + v.y*v.y + v.z*v.z + v.w*v.w;
    #pragma unroll
    for (int o = 16; o; o >>= 1) {
        s  += __shfl_xor_sync(~0u, s, o);
        ss += __shfl_xor_sync(~0u, ss, o);
    }
    if ((t & 31) == 0) { red[t>>5] = s; red[(t>>5)+8] = ss; }
    __syncthreads();
    if (t == 0) {
        float ts=0.f, tss=0.f;
        #pragma unroll
        for (int i = 0; i < 8; ++i) { ts += red[i]; tss += red[i+8]; }
        float mu = ts * (1.f/1024.f);
        red[0] = mu; red[1] = rsqrtf(tss*(1.f/1024.f) - mu*mu + 1e-5f);
    }
    __syncthreads();
    float mu = red[0], rs = red[1];
    float4 wv = ((const float4*)w)[t];
    float4 bv = ((const float4*)b)[t];
    float o0 = (v.x-mu)*rs*wv.x + bv.x, o1 = (v.y-mu)*rs*wv.y + bv.y;
    float o2 = (v.z-mu)*rs*wv.z + bv.z, o3 = (v.w-mu)*rs*wv.w + bv.w;
    __half h0,h1,h2,h3,l0,l1,l2,l3;
    h16split(o0,h0,l0); h16split(o1,h1,l1); h16split(o2,h2,l2); h16split(o3,h3,l3);
    size_t oi = ((size_t)row*1024 + t*4) >> 1;
    __half2 pa, pb;
    pa.x=h0;pa.y=h1;pb.x=h2;pb.y=h3; ((__half2*)yh)[oi]=pa; ((__half2*)yh)[oi+1]=pb;
    pa.x=l0;pa.y=l1;pb.x=l2;pb.y=l3; ((__half2*)yl)[oi]=pa; ((__half2*)yl)[oi+1]=pb;
}

// ---- fp16x2 GEMM: A split (hi/lo), B single; 3-stage, 2 CTAs/SM ----
#define ATILE_B  10240
#define STAGE_H  30720
#define GSMEM_H  (3*STAGE_H)

__device__ __forceinline__ void issue_stage_h(
    const __half* __restrict__ Ah, const __half* __restrict__ Al,
    const __half* __restrict__ Bs,
    uint32_t sbase, int bm, int bn, int ko, int K, int tid)
{
    #pragma unroll
    for (int i = 0; i < 6; ++i) {
        int lin = tid + (i << 8);
        int tile = lin >> 9;
        int wit = lin & 511;
        int r = wit >> 2, ch = wit & 3;
        const __half* gp;
        if      (tile == 0) gp = Ah + (size_t)(bm + r) * K + ko + ch*8;
        else if (tile == 1) gp = Al + (size_t)(bm + r) * K + ko + ch*8;
        else                gp = Bs + (size_t)(bn + r) * K + ko + ch*8;
        CP_ASYNC16(sbase + tile*ATILE_B + r*80 + ch*16, gp);
    }
    CP_COMMIT();
}

// EPI 0: QKV scatter(+bias) q->fp16 split, k/v->fp16 | 1: +bias+res->outf
// EPI 2: h16split(relu(acc+b)*(m>.5)) | 3: res+(acc+b)*m->outf
template<int EPI>
__global__ void __launch_bounds__(256, 2)
tc_gemm16(const __half* __restrict__ Ah, const __half* __restrict__ Al,
          const __half* __restrict__ Bs,
          const float* __restrict__ bias, const float* __restrict__ aux,
          const float* __restrict__ res, float* __restrict__ outf,
          __half* __restrict__ outh, __half* __restrict__ outl, int N, int K)
{
    extern __shared__ char smem[];
    uint32_t sb = s2u(smem);
    const int tid = threadIdx.x, lane = tid & 31, wid = tid >> 5;
    const int wm = wid & 3, wn = wid >> 2;
    const int bm = blockIdx.y << 7, bn = blockIdx.x << 7;

    float acc[2][8][4];
    #pragma unroll
    for (int i = 0; i < 2; ++i)
        #pragma unroll
        for (int j = 0; j < 8; ++j)
            #pragma unroll
            for (int q = 0; q < 4; ++q) acc[i][j][q] = 0.f;

    const int ktn = K >> 5;
    issue_stage_h(Ah, Al, Bs, sb, bm, bn, 0, K, tid);
    if (ktn > 1) issue_stage_h(Ah, Al, Bs, sb + STAGE_H, bm, bn, 32, K, tid);

    const int a_ro = (lane & 15);
    const int a_ko = (lane >> 4) * 8;
    const int b_rp = ((lane >> 4) & 1) * 8 + (lane & 7);
    const int b_ko = ((lane >> 3) & 1) * 8;

    for (int kt = 0; kt < ktn; ++kt) {
        if (kt + 1 < ktn) CP_WAIT1(); else CP_WAIT0();
        __syncthreads();
        if (kt + 2 < ktn)
            issue_stage_h(Ah, Al, Bs, sb + ((kt + 2) % 3) * STAGE_H,
                          bm, bn, (kt + 2) * 32, K, tid);
        uint32_t st = sb + (kt % 3) * STAGE_H;
        #pragma unroll
        for (int ks = 0; ks < 2; ++ks) {
            uint32_t ahi[2][4], alo[2][4], bfr[4][4];
            #pragma unroll
            for (int mf = 0; mf < 2; ++mf) {
                uint32_t ad = st + (wm*32 + mf*16 + a_ro)*80 + (ks*16 + a_ko)*2;
                ldsm4(ahi[mf], ad);
                ldsm4(alo[mf], ad + ATILE_B);
            }
            #pragma unroll
            for (int np = 0; np < 4; ++np)
                ldsm4(bfr[np], st + 2*ATILE_B + (wn*64 + np*16 + b_rp)*80 + (ks*16 + b_ko)*2);
            #pragma unroll
            for (int np = 0; np < 4; ++np)
                #pragma unroll
                for (int mf = 0; mf < 2; ++mf) {
                    mma16816h(acc[mf][np*2  ], ahi[mf], &bfr[np][0]);
                    mma16816h(acc[mf][np*2+1], ahi[mf], &bfr[np][2]);
                }
            #pragma unroll
            for (int np = 0; np < 4; ++np)
                #pragma unroll
                for (int mf = 0; mf < 2; ++mf) {
                    mma16816h(acc[mf][np*2  ], alo[mf], &bfr[np][0]);
                    mma16816h(acc[mf][np*2+1], alo[mf], &bfr[np][2]);
                }
        }
    }

    const int tr = lane >> 2;
    const int tc = (lane & 3) * 2;
    #pragma unroll
    for (int mf = 0; mf < 2; ++mf) {
        #pragma unroll
        for (int nf = 0; nf < 8; ++nf) {
            int gj = bn + wn*64 + nf*8 + tc;
            float2 b2 = *(const float2*)&bias[gj];
            #pragma unroll
            for (int h = 0; h < 2; ++h) {
                int gi = bm + wm*32 + mf*16 + tr + h*8;
                float v0 = acc[mf][nf][h*2]   + b2.x;
                float v1 = acc[mf][nf][h*2+1] + b2.y;
                size_t off = (size_t)gi * N + gj;
                if (EPI == 0) {
                    int wh = gj >> 10, hh = (gj >> 6) & 15, d = gj & 63;
                    int bb = gi >> 10, nn = gi & 1023;
                    size_t idx = (((size_t)(bb*16 + hh))*1024 + nn)*64 + d;
                    if (wh == 0) {
                        __half h0,l0,h1,l1;
                        h16split(v0,h0,l0); h16split(v1,h1,l1);
                        __half2 ph, pl; ph.x=h0; ph.y=h1; pl.x=l0; pl.y=l1;
                        *(__half2*)&g_qh[idx] = ph; *(__half2*)&g_ql[idx] = pl;
                    } else if (wh == 1) {
                        *(__half2*)&g_k16[idx] = __floats2half2_rn(v0, v1);
                    } else {
                        *(__half2*)&g_v[idx] = __floats2half2_rn(v0, v1);
                    }
                } else if (EPI == 1) {
                    float2 rr = *(const float2*)&res[off];
                    float2 o; o.x = v0 + rr.x; o.y = v1 + rr.y;
                    *(float2*)&outf[off] = o;
                } else if (EPI == 2) {
                    float2 m = *(const float2*)&aux[off];
                    v0 = (m.x > 0.5f) ? fmaxf(v0, 0.f) : 0.f;
                    v1 = (m.y > 0.5f) ? fmaxf(v1, 0.f) : 0.f;
                    __half h0,l0,h1,l1;
                    h16split(v0,h0,l0); h16split(v1,h1,l1);
                    __half2 p; p.x=h0; p.y=h1; *(__half2*)&outh[off] = p;
                    p.x=l0; p.y=l1;            *(__half2*)&outl[off] = p;
                } else {
                    float2 m  = *(const float2*)&aux[off];
                    float2 rr = *(const float2*)&res[off];
                    float2 o;
                    o.x = rr.x + ((m.x > 0.5f) ? v0 : 0.f);
                    o.y = rr.y + ((m.y > 0.5f) ? v1 : 0.f);
                    *(float2*)&outf[off] = o;
                }
            }
        }
    }
}

// ------- sparse attention: fp16 Q-split x K-single scores (2 passes) ------
// smem: Q hi/lo 9216 | K 2x18432 | sS 32x1034 f32
#define SS_STR  1034
#define SS_OFF  11520             /* (9216+36864)/4 */
#define ATTN_SMEM (9216 + 36864 + 32*SS_STR*4)

__device__ __forceinline__ void issue_k(uint32_t sb, size_t bhoff, int kt, int buf, int tid) {
    #pragma unroll
    for (int i = 0; i < 2; ++i) {
        int lin = tid + (i << 9);      // 0..1023
        int r = lin >> 3, ch = lin & 7;
        const __half* gsrc = g_k16 + bhoff + (size_t)(kt*128 + r)*64 + ch*8;
        CP_ASYNC16(sb + 9216 + buf*18432 + r*144 + ch*16, gsrc);
    }
    CP_COMMIT();
}

__device__ __forceinline__ float dec(unsigned ub) {
    unsigned fb = ub ^ ((ub & 0x80000000u) ? 0x80000000u : 0xFFFFFFFFu);
    return __uint_as_float(fb);
}

__global__ void __launch_bounds__(512)
attn_kernel()
{
    extern __shared__ char smraw[];
    float* smf = (float*)smraw;
    uint32_t sb = s2u(smraw);

    int blk = blockIdx.x, bh = blk >> 5, n0 = (blk & 31) << 5;
    int tid = threadIdx.x, lane = tid & 31, w = tid >> 5;
    const size_t bhoff = (size_t)bh * 65536;

    {
        int tile = tid >> 8, wit = tid & 255, r = wit >> 3, ch = wit & 7;
        const __half* gsrc = (tile ? g_ql : g_qh) + bhoff + (size_t)(n0 + r)*64 + ch*8;
        *(uint4*)(smraw + tile*4608 + r*144 + ch*16) = *(const uint4*)gsrc;
    }
    issue_k(sb, bhoff, 0, 0, tid);
    __syncthreads();

    const int wm = w & 1, wn = w >> 1;
    const int a_ro = lane & 15, a_ko = (lane >> 4) * 8;
    const int b_rp = ((lane >> 4) & 1) * 8 + (lane & 7);
    const int b_ko = ((lane >> 3) & 1) * 8;
    uint32_t qhi[4][4], qlo[4][4];
    #pragma unroll
    for (int ks = 0; ks < 4; ++ks) {
        uint32_t qa = sb + (wm*16 + a_ro)*144 + (ks*16 + a_ko)*2;
        ldsm4(qhi[ks], qa);
        ldsm4(qlo[ks], qa + 4608);
    }
    const int tr = lane >> 2, tc = (lane & 3) * 2;

    // ---- phase 1: scores via fp16 HMMA (double-buffered K) ----
    for (int kt = 0; kt < 8; ++kt) {
        CP_WAIT0();
        __syncthreads();
        if (kt < 7) issue_k(sb, bhoff, kt + 1, (kt + 1) & 1, tid);
        uint32_t kb = sb + 9216 + (kt & 1)*18432;
        float acc[2][4];
        #pragma unroll
        for (int nf = 0; nf < 2; ++nf)
            #pragma unroll
            for (int q = 0; q < 4; ++q) acc[nf][q] = 0.f;
        #pragma unroll
        for (int ks = 0; ks < 4; ++ks) {
            uint32_t bd = kb + (wn*16 + b_rp)*144 + (ks*16 + b_ko)*2;
            uint32_t bfr[4];
            ldsm4(bfr, bd);
            mma16816h(acc[0], qhi[ks], &bfr[0]);
            mma16816h(acc[1], qhi[ks], &bfr[2]);
            mma16816h(acc[0], qlo[ks], &bfr[0]);
            mma16816h(acc[1], qlo[ks], &bfr[2]);
        }
        #pragma unroll
        for (int nf = 0; nf < 2; ++nf) {
            int key = kt*128 + wn*16 + nf*8 + tc;
            int row0 = wm*16 + tr;
            float2 o;
            o.x = acc[nf][0]*0.125f; o.y = acc[nf][1]*0.125f;
            *(float2*)&smf[SS_OFF + row0*SS_STR + key] = o;
            o.x = acc[nf][2]*0.125f; o.y = acc[nf][3]*0.125f;
            *(float2*)&smf[SS_OFF + (row0+8)*SS_STR + key] = o;
        }
    }
    __syncthreads();

    // ---- per-row: early-exit top-k, softmax, compaction, sparse PV ----
    int r0 = 2 * w;
    float o00=0, o01=0, o10=0, o11=0;
    const __half* Vb = g_v + bhoff;
    #pragma unroll 1
    for (int rr = 0; rr < 2; ++rr) {
        float* srow = &smf[SS_OFF + (r0 + rr) * SS_STR];
        unsigned key[32];
        float lmax = -3.4e38f;
        #pragma unroll
        for (int i = 0; i < 32; ++i) {
            float s = srow[lane + 32*i];
            lmax = fmaxf(lmax, s);
            unsigned ub = __float_as_uint(s);
            key[i] = ub ^ (((unsigned)((int)ub >> 31)) | 0x80000000u);
        }
        #pragma unroll
        for (int o = 16; o; o >>= 1) lmax = fmaxf(lmax, __shfl_xor_sync(~0u, lmax, o));

        unsigned T;
        {
            unsigned lo = 0u, hi = 0xFFFFFFFFu;
            while (lo < hi) {
                unsigned mid = lo + (unsigned)(((unsigned long long)(hi - lo) + 1ull) >> 1);
                unsigned c = 0;
                #pragma unroll
                for (int i = 0; i < 32; ++i) c += (key[i] >= mid) ? 1u : 0u;
                c = __reduce_add_sync(~0u, c);
                if (c == (unsigned)KSP) { lo = mid; break; }
                if (c > (unsigned)KSP) lo = mid; else hi = mid - 1u;
            }
            T = lo;
        }

        float lsum = 0.f;
        #pragma unroll
        for (int i = 0; i < 32; ++i) {
            if (key[i] >= T) lsum += __expf(dec(key[i]) - lmax);
        }
        #pragma unroll
        for (int o = 16; o; o >>= 1) lsum += __shfl_xor_sync(~0u, lsum, o);
        float inv = 1.f / lsum;

        uint2* lst = (uint2*)srow;
        int cnt = 0;
        #pragma unroll
        for (int i = 0; i < 32; ++i) {
            bool sel = key[i] >= T;
            unsigned mask = __ballot_sync(~0u, sel);
            if (sel) {
                int ofs = cnt + __popc(mask & ((1u << lane) - 1u));
                float p = __expf(dec(key[i]) - lmax) * inv;
                if (ofs < 128) {
                    uint2 e; e.x = __float_as_uint(p); e.y = (unsigned)(lane + 32*i);
                    lst[ofs] = e;
                }
            }
            cnt += __popc(mask);
        }
        if (cnt > 128) cnt = 128;
        __syncwarp();

        float a0 = 0.f, a1 = 0.f;
        #pragma unroll 4
        for (int j = 0; j < cnt; ++j) {
            uint2 e = lst[j];
            float p = __uint_as_float(e.x);
            __half2 hv = __ldg((const __half2*)(Vb + (size_t)e.y * 64) + lane);
            float2 v = __half22float2(hv);
            a0 = fmaf(p, v.x, a0);
            a1 = fmaf(p, v.y, a1);
        }
        if (rr == 0) { o00 = a0; o01 = a1; } else { o10 = a0; o11 = a1; }
    }

    int bb = bh >> 4, hh = bh & 15;
    {
        size_t base0 = ((size_t)(bb*1024 + n0 + r0    )) * 1024 + hh*64 + lane*2;
        size_t base1 = ((size_t)(bb*1024 + n0 + r0 + 1)) * 1024 + hh*64 + lane*2;
        __half h0, l0, h1, l1;
        h16split(o00, h0, l0); h16split(o01, h1, l1);
        __half2 ph, pl; ph.x = h0; ph.y = h1; pl.x = l0; pl.y = l1;
        *(__half2*)&g_ath[base0] = ph; *(__half2*)&g_atl[base0] = pl;
        h16split(o10, h0, l0); h16split(o11, h1, l1);
        ph.x = h0; ph.y = h1; pl.x = l0; pl.y = l1;
        *(__half2*)&g_ath[base1] = ph; *(__half2*)&g_atl[base1] = pl;
    }
}

// ---------------- launch ----------------
extern "C" void kernel_launch(void* const* d_in, const int* in_sizes, int n_in,
                              void* d_out, int out_size)
{
    (void)in_sizes; (void)n_in; (void)out_size;
    const float* x     = (const float*)d_in[0];
    const float* ln1_w = (const float*)d_in[1];
    const float* ln1_b = (const float*)d_in[2];
    const float* qkv_w = (const float*)d_in[3];
    const float* qkv_b = (const float*)d_in[4];
    const float* out_w = (const float*)d_in[5];
    const float* out_b = (const float*)d_in[6];
    const float* ln2_w = (const float*)d_in[7];
    const float* ln2_b = (const float*)d_in[8];
    const float* w1    = (const float*)d_in[9];
    const float* b1    = (const float*)d_in[10];
    const float* w2    = (const float*)d_in[11];
    const float* b2    = (const float*)d_in[12];
    const float* mask1 = (const float*)d_in[13];
    const float* mask2 = (const float*)d_in[14];
    float* out = (float*)d_out;

    void *x1, *xnh, *xnl, *hnh, *hnl, *ath, *atl, *h1h, *h1l,
         *qw16, *ow16, *w116, *w216;
    cudaGetSymbolAddress(&x1, g_x1);
    cudaGetSymbolAddress(&xnh, g_xnh); cudaGetSymbolAddress(&xnl, g_xnl);
    cudaGetSymbolAddress(&hnh, g_hnh); cudaGetSymbolAddress(&hnl, g_hnl);
    cudaGetSymbolAddress(&ath, g_ath); cudaGetSymbolAddress(&atl, g_atl);
    cudaGetSymbolAddress(&h1h, g_h1h); cudaGetSymbolAddress(&h1l, g_h1l);
    cudaGetSymbolAddress(&qw16, g_qw16);
    cudaGetSymbolAddress(&ow16, g_ow16);
    cudaGetSymbolAddress(&w116, g_w116);
    cudaGetSymbolAddress(&w216, g_w216);

    cudaFuncSetAttribute(attn_kernel, cudaFuncAttributeMaxDynamicSharedMemorySize, ATTN_SMEM);
    cudaFuncSetAttribute(tc_gemm16<0>, cudaFuncAttributeMaxDynamicSharedMemorySize, GSMEM_H);
    cudaFuncSetAttribute(tc_gemm16<1>, cudaFuncAttributeMaxDynamicSharedMemorySize, GSMEM_H);
    cudaFuncSetAttribute(tc_gemm16<2>, cudaFuncAttributeMaxDynamicSharedMemorySize, GSMEM_H);
    cudaFuncSetAttribute(tc_gemm16<3>, cudaFuncAttributeMaxDynamicSharedMemorySize, GSMEM_H);

    // order: [0]cvt [1]ln1 [2]gemm0 [3]attn  -> ncu captures attn
    cvt_w16<<<12288, 256>>>(qkv_w, (__half*)qw16, 786432,
                            out_w, (__half*)ow16, 262144,
                            w1,    (__half*)w116, 1048576,
                            w2,    (__half*)w216, 1048576);

    ln_f16<<<M_, 256>>>(x, ln1_w, ln1_b, (__half*)xnh, (__half*)xnl);

    tc_gemm16<0><<<dim3(24, 64), 256, GSMEM_H>>>((__half*)xnh, (__half*)xnl,
        (__half*)qw16, qkv_b, nullptr, nullptr, nullptr, nullptr, nullptr, 3*C_, C_);

    attn_kernel<<<BH_*(N_/32), 512, ATTN_SMEM>>>();

    tc_gemm16<1><<<dim3(8, 64), 256, GSMEM_H>>>((__half*)ath, (__half*)atl,
        (__half*)ow16, out_b, nullptr, x, (float*)x1, nullptr, nullptr, C_, C_);

    ln_f16<<<M_, 256>>>((float*)x1, ln2_w, ln2_b, (__half*)hnh, (__half*)hnl);

    tc_gemm16<2><<<dim3(32, 64), 256, GSMEM_H>>>((__half*)hnh, (__half*)hnl,
        (__half*)w116, b1, mask1, nullptr, nullptr, (__half*)h1h, (__half*)h1l, FF_, C_);

    tc_gemm16<3><<<dim3(8, 64), 256, GSMEM_H>>>((__half*)h1h, (__half*)h1l,
        (__half*)w216, b2, mask2, (float*)x1, out, nullptr, nullptr, C_, FF_);
}

// round 15
// speedup vs baseline: 1.3284x; 1.0361x over previous
#include <cuda_runtime.h>
#include <cuda_fp16.h>
#include <stdint.h>

#define B_   8
#define N_   1024
#define C_   1024
#define HD_  64
#define FF_  4096
#define BH_  128
#define M_   8192
#define KSP  102

// ---------------- scratch ----------------
__device__ __align__(256) __half g_v[(size_t)BH_*N_*HD_];
__device__ __align__(256) float g_x1[(size_t)M_*C_];
__device__ __align__(256) __half g_qh[(size_t)BH_*N_*HD_], g_ql[(size_t)BH_*N_*HD_];
__device__ __align__(256) __half g_k16[(size_t)BH_*N_*HD_];
__device__ __align__(256) __half g_xnh[(size_t)M_*C_],  g_xnl[(size_t)M_*C_];
__device__ __align__(256) __half g_hnh[(size_t)M_*C_],  g_hnl[(size_t)M_*C_];
__device__ __align__(256) __half g_ath[(size_t)M_*C_],  g_atl[(size_t)M_*C_];
__device__ __align__(256) __half g_h1h[(size_t)M_*FF_], g_h1l[(size_t)M_*FF_];
__device__ __align__(256) __half g_qw16[(size_t)3*C_*C_];
__device__ __align__(256) __half g_ow16[(size_t)C_*C_];
__device__ __align__(256) __half g_w116[(size_t)FF_*C_];
__device__ __align__(256) __half g_w216[(size_t)C_*FF_];

// ---------------- helpers ----------------
__device__ __forceinline__ uint32_t s2u(const void* p) {
    uint32_t a;
    asm("{ .reg .u64 t; cvta.to.shared.u64 t, %1; cvt.u32.u64 %0, t; }" : "=r"(a) : "l"(p));
    return a;
}
__device__ __forceinline__ void h16split(float v, __half& h, __half& l) {
    h = __float2half_rn(v);
    l = __float2half_rn(v - __half2float(h));
}
__device__ __forceinline__ void ldsm4(uint32_t* r, uint32_t a) {
    asm volatile("ldmatrix.sync.aligned.m8n8.x4.shared.b16 {%0,%1,%2,%3}, [%4];"
        : "=r"(r[0]), "=r"(r[1]), "=r"(r[2]), "=r"(r[3]) : "r"(a));
}
__device__ __forceinline__ void mma16816h(float* c, const uint32_t* a, const uint32_t* b) {
    asm volatile("mma.sync.aligned.m16n8k16.row.col.f32.f16.f16.f32 "
        "{%0,%1,%2,%3}, {%4,%5,%6,%7}, {%8,%9}, {%0,%1,%2,%3};"
        : "+f"(c[0]), "+f"(c[1]), "+f"(c[2]), "+f"(c[3])
        : "r"(a[0]), "r"(a[1]), "r"(a[2]), "r"(a[3]), "r"(b[0]), "r"(b[1]));
}
#define CP_ASYNC16(s, g) \
    asm volatile("cp.async.cg.shared.global [%0], [%1], 16;" :: "r"(s), "l"(g))
#define CP_COMMIT() asm volatile("cp.async.commit_group;" ::: "memory")
#define CP_WAIT0()  asm volatile("cp.async.wait_group 0;" ::: "memory")
#define CP_WAIT1()  asm volatile("cp.async.wait_group 1;" ::: "memory")

// ---------------- weight conversion: all weights -> fp16 ----------------
__global__ void __launch_bounds__(256)
cvt_w16(const float* __restrict__ s0, __half* __restrict__ d0, int n0,
        const float* __restrict__ s1, __half* __restrict__ d1, int n1,
        const float* __restrict__ s2, __half* __restrict__ d2, int n2,
        const float* __restrict__ s3, __half* __restrict__ d3, int n3)
{
    int i = blockIdx.x * 256 + threadIdx.x;
    const float* s; __half* d;
    if (i < n0) { s = s0; d = d0; }
    else if ((i -= n0) < n1) { s = s1; d = d1; }
    else if ((i -= n1) < n2) { s = s2; d = d2; }
    else { i -= n2; if (i >= n3) return; s = s3; d = d3; }
    float4 v = ((const float4*)s)[i];
    ((__half2*)d)[i*2]   = __floats2half2_rn(v.x, v.y);
    ((__half2*)d)[i*2+1] = __floats2half2_rn(v.z, v.w);
}

// ---------------- LayerNorm -> fp16 hi/lo ----------------
__global__ void __launch_bounds__(256)
ln_f16(const float* __restrict__ x, const float* __restrict__ w,
       const float* __restrict__ b, __half* __restrict__ yh, __half* __restrict__ yl)
{
    __shared__ float red[16];
    int row = blockIdx.x, t = threadIdx.x;
    float4 v = ((const float4*)(x + (size_t)row * 1024))[t];
    float s  = v.x + v.y + v.z + v.w;
    float ss = v.x*v.x + v.y*v.y + v.z*v.z + v.w*v.w;
    #pragma unroll
    for (int o = 16; o; o >>= 1) {
        s  += __shfl_xor_sync(~0u, s, o);
        ss += __shfl_xor_sync(~0u, ss, o);
    }
    if ((t & 31) == 0) { red[t>>5] = s; red[(t>>5)+8] = ss; }
    __syncthreads();
    if (t == 0) {
        float ts=0.f, tss=0.f;
        #pragma unroll
        for (int i = 0; i < 8; ++i) { ts += red[i]; tss += red[i+8]; }
        float mu = ts * (1.f/1024.f);
        red[0] = mu; red[1] = rsqrtf(tss*(1.f/1024.f) - mu*mu + 1e-5f);
    }
    __syncthreads();
    float mu = red[0], rs = red[1];
    float4 wv = ((const float4*)w)[t];
    float4 bv = ((const float4*)b)[t];
    float o0 = (v.x-mu)*rs*wv.x + bv.x, o1 = (v.y-mu)*rs*wv.y + bv.y;
    float o2 = (v.z-mu)*rs*wv.z + bv.z, o3 = (v.w-mu)*rs*wv.w + bv.w;
    __half h0,h1,h2,h3,l0,l1,l2,l3;
    h16split(o0,h0,l0); h16split(o1,h1,l1); h16split(o2,h2,l2); h16split(o3,h3,l3);
    size_t oi = ((size_t)row*1024 + t*4) >> 1;
    __half2 pa, pb;
    pa.x=h0;pa.y=h1;pb.x=h2;pb.y=h3; ((__half2*)yh)[oi]=pa; ((__half2*)yh)[oi+1]=pb;
    pa.x=l0;pa.y=l1;pb.x=l2;pb.y=l3; ((__half2*)yl)[oi]=pa; ((__half2*)yl)[oi+1]=pb;
}

// ---- fp16x2 GEMM: A split (hi/lo), B single; 3-stage, 2 CTAs/SM ----
#define ATILE_B  10240
#define STAGE_H  30720
#define GSMEM_H  (3*STAGE_H)

__device__ __forceinline__ void issue_stage_h(
    const __half* __restrict__ Ah, const __half* __restrict__ Al,
    const __half* __restrict__ Bs,
    uint32_t sbase, int bm, int bn, int ko, int K, int tid)
{
    #pragma unroll
    for (int i = 0; i < 6; ++i) {
        int lin = tid + (i << 8);
        int tile = lin >> 9;
        int wit = lin & 511;
        int r = wit >> 2, ch = wit & 3;
        const __half* gp;
        if      (tile == 0) gp = Ah + (size_t)(bm + r) * K + ko + ch*8;
        else if (tile == 1) gp = Al + (size_t)(bm + r) * K + ko + ch*8;
        else                gp = Bs + (size_t)(bn + r) * K + ko + ch*8;
        CP_ASYNC16(sbase + tile*ATILE_B + r*80 + ch*16, gp);
    }
    CP_COMMIT();
}

// EPI 0: QKV scatter(+bias) | 1: +bias+res->outf | 2: split(relu·mask) | 3: res+acc·mask
template<int EPI>
__global__ void __launch_bounds__(256, 2)
tc_gemm16(const __half* __restrict__ Ah, const __half* __restrict__ Al,
          const __half* __restrict__ Bs,
          const float* __restrict__ bias, const float* __restrict__ aux,
          const float* __restrict__ res, float* __restrict__ outf,
          __half* __restrict__ outh, __half* __restrict__ outl, int N, int K)
{
    extern __shared__ char smem[];
    uint32_t sb = s2u(smem);
    const int tid = threadIdx.x, lane = tid & 31, wid = tid >> 5;
    const int wm = wid & 3, wn = wid >> 2;
    const int bm = blockIdx.y << 7, bn = blockIdx.x << 7;

    float acc[2][8][4];
    #pragma unroll
    for (int i = 0; i < 2; ++i)
        #pragma unroll
        for (int j = 0; j < 8; ++j)
            #pragma unroll
            for (int q = 0; q < 4; ++q) acc[i][j][q] = 0.f;

    const int ktn = K >> 5;
    issue_stage_h(Ah, Al, Bs, sb, bm, bn, 0, K, tid);
    if (ktn > 1) issue_stage_h(Ah, Al, Bs, sb + STAGE_H, bm, bn, 32, K, tid);

    const int a_ro = (lane & 15);
    const int a_ko = (lane >> 4) * 8;
    const int b_rp = ((lane >> 4) & 1) * 8 + (lane & 7);
    const int b_ko = ((lane >> 3) & 1) * 8;

    for (int kt = 0; kt < ktn; ++kt) {
        if (kt + 1 < ktn) CP_WAIT1(); else CP_WAIT0();
        __syncthreads();
        if (kt + 2 < ktn)
            issue_stage_h(Ah, Al, Bs, sb + ((kt + 2) % 3) * STAGE_H,
                          bm, bn, (kt + 2) * 32, K, tid);
        uint32_t st = sb + (kt % 3) * STAGE_H;
        #pragma unroll
        for (int ks = 0; ks < 2; ++ks) {
            uint32_t ahi[2][4], alo[2][4], bfr[4][4];
            #pragma unroll
            for (int mf = 0; mf < 2; ++mf) {
                uint32_t ad = st + (wm*32 + mf*16 + a_ro)*80 + (ks*16 + a_ko)*2;
                ldsm4(ahi[mf], ad);
                ldsm4(alo[mf], ad + ATILE_B);
            }
            #pragma unroll
            for (int np = 0; np < 4; ++np)
                ldsm4(bfr[np], st + 2*ATILE_B + (wn*64 + np*16 + b_rp)*80 + (ks*16 + b_ko)*2);
            #pragma unroll
            for (int np = 0; np < 4; ++np)
                #pragma unroll
                for (int mf = 0; mf < 2; ++mf) {
                    mma16816h(acc[mf][np*2  ], ahi[mf], &bfr[np][0]);
                    mma16816h(acc[mf][np*2+1], ahi[mf], &bfr[np][2]);
                }
            #pragma unroll
            for (int np = 0; np < 4; ++np)
                #pragma unroll
                for (int mf = 0; mf < 2; ++mf) {
                    mma16816h(acc[mf][np*2  ], alo[mf], &bfr[np][0]);
                    mma16816h(acc[mf][np*2+1], alo[mf], &bfr[np][2]);
                }
        }
    }

    const int tr = lane >> 2;
    const int tc = (lane & 3) * 2;
    #pragma unroll
    for (int mf = 0; mf < 2; ++mf) {
        #pragma unroll
        for (int nf = 0; nf < 8; ++nf) {
            int gj = bn + wn*64 + nf*8 + tc;
            float2 b2 = *(const float2*)&bias[gj];
            #pragma unroll
            for (int h = 0; h < 2; ++h) {
                int gi = bm + wm*32 + mf*16 + tr + h*8;
                float v0 = acc[mf][nf][h*2]   + b2.x;
                float v1 = acc[mf][nf][h*2+1] + b2.y;
                size_t off = (size_t)gi * N + gj;
                if (EPI == 0) {
                    int wh = gj >> 10, hh = (gj >> 6) & 15, d = gj & 63;
                    int bb = gi >> 10, nn = gi & 1023;
                    size_t idx = (((size_t)(bb*16 + hh))*1024 + nn)*64 + d;
                    if (wh == 0) {
                        __half h0,l0,h1,l1;
                        h16split(v0,h0,l0); h16split(v1,h1,l1);
                        __half2 ph, pl; ph.x=h0; ph.y=h1; pl.x=l0; pl.y=l1;
                        *(__half2*)&g_qh[idx] = ph; *(__half2*)&g_ql[idx] = pl;
                    } else if (wh == 1) {
                        *(__half2*)&g_k16[idx] = __floats2half2_rn(v0, v1);
                    } else {
                        *(__half2*)&g_v[idx] = __floats2half2_rn(v0, v1);
                    }
                } else if (EPI == 1) {
                    float2 rr = *(const float2*)&res[off];
                    float2 o; o.x = v0 + rr.x; o.y = v1 + rr.y;
                    *(float2*)&outf[off] = o;
                } else if (EPI == 2) {
                    float2 m = *(const float2*)&aux[off];
                    v0 = (m.x > 0.5f) ? fmaxf(v0, 0.f) : 0.f;
                    v1 = (m.y > 0.5f) ? fmaxf(v1, 0.f) : 0.f;
                    __half h0,l0,h1,l1;
                    h16split(v0,h0,l0); h16split(v1,h1,l1);
                    __half2 p; p.x=h0; p.y=h1; *(__half2*)&outh[off] = p;
                    p.x=l0; p.y=l1;            *(__half2*)&outl[off] = p;
                } else {
                    float2 m  = *(const float2*)&aux[off];
                    float2 rr = *(const float2*)&res[off];
                    float2 o;
                    o.x = rr.x + ((m.x > 0.5f) ? v0 : 0.f);
                    o.y = rr.y + ((m.y > 0.5f) ? v1 : 0.f);
                    *(float2*)&outf[off] = o;
                }
            }
        }
    }
}

// ------- sparse attention: fp16 scores, scan-compacted selection ----------
#define SS_STR  1034
#define SS_OFF  11520
#define ATTN_SMEM (9216 + 36864 + 32*SS_STR*4)

__device__ __forceinline__ void issue_k(uint32_t sb, size_t bhoff, int kt, int buf, int tid) {
    #pragma unroll
    for (int i = 0; i < 2; ++i) {
        int lin = tid + (i << 9);
        int r = lin >> 3, ch = lin & 7;
        const __half* gsrc = g_k16 + bhoff + (size_t)(kt*128 + r)*64 + ch*8;
        CP_ASYNC16(sb + 9216 + buf*18432 + r*144 + ch*16, gsrc);
    }
    CP_COMMIT();
}

__device__ __forceinline__ float dec(unsigned ub) {
    unsigned fb = ub ^ ((ub & 0x80000000u) ? 0x80000000u : 0xFFFFFFFFu);
    return __uint_as_float(fb);
}

__global__ void __launch_bounds__(512)
attn_kernel()
{
    extern __shared__ char smraw[];
    float* smf = (float*)smraw;
    uint32_t sb = s2u(smraw);

    int blk = blockIdx.x, bh = blk >> 5, n0 = (blk & 31) << 5;
    int tid = threadIdx.x, lane = tid & 31, w = tid >> 5;
    const size_t bhoff = (size_t)bh * 65536;

    {
        int tile = tid >> 8, wit = tid & 255, r = wit >> 3, ch = wit & 7;
        const __half* gsrc = (tile ? g_ql : g_qh) + bhoff + (size_t)(n0 + r)*64 + ch*8;
        *(uint4*)(smraw + tile*4608 + r*144 + ch*16) = *(const uint4*)gsrc;
    }
    issue_k(sb, bhoff, 0, 0, tid);
    __syncthreads();

    const int wm = w & 1, wn = w >> 1;
    const int a_ro = lane & 15, a_ko = (lane >> 4) * 8;
    const int b_rp = ((lane >> 4) & 1) * 8 + (lane & 7);
    const int b_ko = ((lane >> 3) & 1) * 8;
    uint32_t qhi[4][4], qlo[4][4];
    #pragma unroll
    for (int ks = 0; ks < 4; ++ks) {
        uint32_t qa = sb + (wm*16 + a_ro)*144 + (ks*16 + a_ko)*2;
        ldsm4(qhi[ks], qa);
        ldsm4(qlo[ks], qa + 4608);
    }
    const int tr = lane >> 2, tc = (lane & 3) * 2;

    // ---- phase 1: scores via fp16 HMMA (double-buffered K) ----
    for (int kt = 0; kt < 8; ++kt) {
        CP_WAIT0();
        __syncthreads();
        if (kt < 7) issue_k(sb, bhoff, kt + 1, (kt + 1) & 1, tid);
        uint32_t kb = sb + 9216 + (kt & 1)*18432;
        float acc[2][4];
        #pragma unroll
        for (int nf = 0; nf < 2; ++nf)
            #pragma unroll
            for (int q = 0; q < 4; ++q) acc[nf][q] = 0.f;
        #pragma unroll
        for (int ks = 0; ks < 4; ++ks) {
            uint32_t bd = kb + (wn*16 + b_rp)*144 + (ks*16 + b_ko)*2;
            uint32_t bfr[4];
            ldsm4(bfr, bd);
            mma16816h(acc[0], qhi[ks], &bfr[0]);
            mma16816h(acc[1], qhi[ks], &bfr[2]);
            mma16816h(acc[0], qlo[ks], &bfr[0]);
            mma16816h(acc[1], qlo[ks], &bfr[2]);
        }
        #pragma unroll
        for (int nf = 0; nf < 2; ++nf) {
            int key = kt*128 + wn*16 + nf*8 + tc;
            int row0 = wm*16 + tr;
            float2 o;
            o.x = acc[nf][0]*0.125f; o.y = acc[nf][1]*0.125f;
            *(float2*)&smf[SS_OFF + row0*SS_STR + key] = o;
            o.x = acc[nf][2]*0.125f; o.y = acc[nf][3]*0.125f;
            *(float2*)&smf[SS_OFF + (row0+8)*SS_STR + key] = o;
        }
    }
    __syncthreads();

    // ---- per-row: early-exit top-k, scan compaction, unnormalized PV ----
    int r0 = 2 * w;
    float o00=0, o01=0, o10=0, o11=0;
    const __half* Vb = g_v + bhoff;
    #pragma unroll 1
    for (int rr = 0; rr < 2; ++rr) {
        float* srow = &smf[SS_OFF + (r0 + rr) * SS_STR];
        unsigned key[32];
        float lmax = -3.4e38f;
        #pragma unroll
        for (int i = 0; i < 32; ++i) {
            float s = srow[lane + 32*i];
            lmax = fmaxf(lmax, s);
            unsigned ub = __float_as_uint(s);
            key[i] = ub ^ (((unsigned)((int)ub >> 31)) | 0x80000000u);
        }
        #pragma unroll
        for (int o = 16; o; o >>= 1) lmax = fmaxf(lmax, __shfl_xor_sync(~0u, lmax, o));

        unsigned T;
        {
            unsigned lo = 0u, hi = 0xFFFFFFFFu;
            while (lo < hi) {
                unsigned mid = lo + (unsigned)(((unsigned long long)(hi - lo) + 1ull) >> 1);
                unsigned c = 0;
                #pragma unroll
                for (int i = 0; i < 32; ++i) c += (key[i] >= mid) ? 1u : 0u;
                c = __reduce_add_sync(~0u, c);
                if (c == (unsigned)KSP) { lo = mid; break; }
                if (c > (unsigned)KSP) lo = mid; else hi = mid - 1u;
            }
            T = lo;
        }

        // selection mask (bit-exact same selection as before)
        unsigned selmask = 0u;
        #pragma unroll
        for (int i = 0; i < 32; ++i)
            if (key[i] >= T) selmask |= (1u << i);
        int c = __popc(selmask);

        // exclusive warp scan of per-lane counts
        int off = c;
        #pragma unroll
        for (int o = 1; o < 32; o <<= 1) {
            int nsh = __shfl_up_sync(~0u, off, o);
            if (lane >= o) off += nsh;
        }
        int total = __shfl_sync(~0u, off, 31);
        off -= c;
        int cnt = total > 128 ? 128 : total;

        // selected-only: exp once, write unnormalized (e, pos), accumulate lsum
        uint2* lst = (uint2*)srow;
        float lsum = 0.f;
        unsigned m = selmask;
        while (m) {
            int i = __ffs(m) - 1;
            m &= m - 1u;
            float e = __expf(dec(key[i]) - lmax);
            lsum += e;
            if (off < 128) {
                uint2 en; en.x = __float_as_uint(e); en.y = (unsigned)(lane + 32*i);
                lst[off] = en;
            }
            ++off;
        }
        #pragma unroll
        for (int o = 16; o; o >>= 1) lsum += __shfl_xor_sync(~0u, lsum, o);
        float inv = 1.f / lsum;
        __syncwarp();

        // sparse PV with unnormalized weights; scale at end
        float a0 = 0.f, a1 = 0.f;
        #pragma unroll 4
        for (int j = 0; j < cnt; ++j) {
            uint2 e = lst[j];
            float p = __uint_as_float(e.x);
            __half2 hv = __ldg((const __half2*)(Vb + (size_t)e.y * 64) + lane);
            float2 v = __half22float2(hv);
            a0 = fmaf(p, v.x, a0);
            a1 = fmaf(p, v.y, a1);
        }
        a0 *= inv;
        a1 *= inv;
        if (rr == 0) { o00 = a0; o01 = a1; } else { o10 = a0; o11 = a1; }
    }

    int bb = bh >> 4, hh = bh & 15;
    {
        size_t base0 = ((size_t)(bb*1024 + n0 + r0    )) * 1024 + hh*64 + lane*2;
        size_t base1 = ((size_t)(bb*1024 + n0 + r0 + 1)) * 1024 + hh*64 + lane*2;
        __half h0, l0, h1, l1;
        h16split(o00, h0, l0); h16split(o01, h1, l1);
        __half2 ph, pl; ph.x = h0; ph.y = h1; pl.x = l0; pl.y = l1;
        *(__half2*)&g_ath[base0] = ph; *(__half2*)&g_atl[base0] = pl;
        h16split(o10, h0, l0); h16split(o11, h1, l1);
        ph.x = h0; ph.y = h1; pl.x = l0; pl.y = l1;
        *(__half2*)&g_ath[base1] = ph; *(__half2*)&g_atl[base1] = pl;
    }
}

// ---------------- launch ----------------
extern "C" void kernel_launch(void* const* d_in, const int* in_sizes, int n_in,
                              void* d_out, int out_size)
{
    (void)in_sizes; (void)n_in; (void)out_size;
    const float* x     = (const float*)d_in[0];
    const float* ln1_w = (const float*)d_in[1];
    const float* ln1_b = (const float*)d_in[2];
    const float* qkv_w = (const float*)d_in[3];
    const float* qkv_b = (const float*)d_in[4];
    const float* out_w = (const float*)d_in[5];
    const float* out_b = (const float*)d_in[6];
    const float* ln2_w = (const float*)d_in[7];
    const float* ln2_b = (const float*)d_in[8];
    const float* w1    = (const float*)d_in[9];
    const float* b1    = (const float*)d_in[10];
    const float* w2    = (const float*)d_in[11];
    const float* b2    = (const float*)d_in[12];
    const float* mask1 = (const float*)d_in[13];
    const float* mask2 = (const float*)d_in[14];
    float* out = (float*)d_out;

    void *x1, *xnh, *xnl, *hnh, *hnl, *ath, *atl, *h1h, *h1l,
         *qw16, *ow16, *w116, *w216;
    cudaGetSymbolAddress(&x1, g_x1);
    cudaGetSymbolAddress(&xnh, g_xnh); cudaGetSymbolAddress(&xnl, g_xnl);
    cudaGetSymbolAddress(&hnh, g_hnh); cudaGetSymbolAddress(&hnl, g_hnl);
    cudaGetSymbolAddress(&ath, g_ath); cudaGetSymbolAddress(&atl, g_atl);
    cudaGetSymbolAddress(&h1h, g_h1h); cudaGetSymbolAddress(&h1l, g_h1l);
    cudaGetSymbolAddress(&qw16, g_qw16);
    cudaGetSymbolAddress(&ow16, g_ow16);
    cudaGetSymbolAddress(&w116, g_w116);
    cudaGetSymbolAddress(&w216, g_w216);

    cudaFuncSetAttribute(attn_kernel, cudaFuncAttributeMaxDynamicSharedMemorySize, ATTN_SMEM);
    cudaFuncSetAttribute(tc_gemm16<0>, cudaFuncAttributeMaxDynamicSharedMemorySize, GSMEM_H);
    cudaFuncSetAttribute(tc_gemm16<1>, cudaFuncAttributeMaxDynamicSharedMemorySize, GSMEM_H);
    cudaFuncSetAttribute(tc_gemm16<2>, cudaFuncAttributeMaxDynamicSharedMemorySize, GSMEM_H);
    cudaFuncSetAttribute(tc_gemm16<3>, cudaFuncAttributeMaxDynamicSharedMemorySize, GSMEM_H);

    // order: [0]cvt [1]ln1 [2]gemm0 [3]attn  -> ncu captures attn
    cvt_w16<<<12288, 256>>>(qkv_w, (__half*)qw16, 786432,
                            out_w, (__half*)ow16, 262144,
                            w1,    (__half*)w116, 1048576,
                            w2,    (__half*)w216, 1048576);

    ln_f16<<<M_, 256>>>(x, ln1_w, ln1_b, (__half*)xnh, (__half*)xnl);

    tc_gemm16<0><<<dim3(24, 64), 256, GSMEM_H>>>((__half*)xnh, (__half*)xnl,
        (__half*)qw16, qkv_b, nullptr, nullptr, nullptr, nullptr, nullptr, 3*C_, C_);

    attn_kernel<<<BH_*(N_/32), 512, ATTN_SMEM>>>();

    tc_gemm16<1><<<dim3(8, 64), 256, GSMEM_H>>>((__half*)ath, (__half*)atl,
        (__half*)ow16, out_b, nullptr, x, (float*)x1, nullptr, nullptr, C_, C_);

    ln_f16<<<M_, 256>>>((float*)x1, ln2_w, ln2_b, (__half*)hnh, (__half*)hnl);

    tc_gemm16<2><<<dim3(32, 64), 256, GSMEM_H>>>((__half*)hnh, (__half*)hnl,
        (__half*)w116, b1, mask1, nullptr, nullptr, (__half*)h1h, (__half*)h1l, FF_, C_);

    tc_gemm16<3><<<dim3(8, 64), 256, GSMEM_H>>>((__half*)h1h, (__half*)h1l,
        (__half*)w216, b2, mask2, (float*)x1, out, nullptr, nullptr, C_, FF_);
}

// round 16
// speedup vs baseline: 1.4007x; 1.0544x over previous
#include <cuda_runtime.h>
#include <cuda_fp16.h>
#include <stdint.h>

#define B_   8
#define N_   1024
#define C_   1024
#define HD_  64
#define FF_  4096
#define BH_  128
#define M_   8192
#define KSP  102

// ---------------- scratch ----------------
__device__ __align__(256) __half g_v[(size_t)BH_*N_*HD_];
__device__ __align__(256) float g_x1[(size_t)M_*C_];
__device__ __align__(256) __half g_qh[(size_t)BH_*N_*HD_], g_ql[(size_t)BH_*N_*HD_];
__device__ __align__(256) __half g_k16[(size_t)BH_*N_*HD_];
__device__ __align__(256) __half g_xnh[(size_t)M_*C_],  g_xnl[(size_t)M_*C_];
__device__ __align__(256) __half g_hnh[(size_t)M_*C_],  g_hnl[(size_t)M_*C_];
__device__ __align__(256) __half g_ath[(size_t)M_*C_],  g_atl[(size_t)M_*C_];
__device__ __align__(256) __half g_h1h[(size_t)M_*FF_], g_h1l[(size_t)M_*FF_];
__device__ __align__(256) __half g_qw16[(size_t)3*C_*C_];
__device__ __align__(256) __half g_ow16[(size_t)C_*C_];
__device__ __align__(256) __half g_w116[(size_t)FF_*C_];
__device__ __align__(256) __half g_w216[(size_t)C_*FF_];

// ---------------- helpers ----------------
__device__ __forceinline__ uint32_t s2u(const void* p) {
    uint32_t a;
    asm("{ .reg .u64 t; cvta.to.shared.u64 t, %1; cvt.u32.u64 %0, t; }" : "=r"(a) : "l"(p));
    return a;
}
__device__ __forceinline__ void h16split(float v, __half& h, __half& l) {
    h = __float2half_rn(v);
    l = __float2half_rn(v - __half2float(h));
}
__device__ __forceinline__ void ldsm4(uint32_t* r, uint32_t a) {
    asm volatile("ldmatrix.sync.aligned.m8n8.x4.shared.b16 {%0,%1,%2,%3}, [%4];"
        : "=r"(r[0]), "=r"(r[1]), "=r"(r[2]), "=r"(r[3]) : "r"(a));
}
__device__ __forceinline__ void mma16816h(float* c, const uint32_t* a, const uint32_t* b) {
    asm volatile("mma.sync.aligned.m16n8k16.row.col.f32.f16.f16.f32 "
        "{%0,%1,%2,%3}, {%4,%5,%6,%7}, {%8,%9}, {%0,%1,%2,%3};"
        : "+f"(c[0]), "+f"(c[1]), "+f"(c[2]), "+f"(c[3])
        : "r"(a[0]), "r"(a[1]), "r"(a[2]), "r"(a[3]), "r"(b[0]), "r"(b[1]));
}
#define CP_ASYNC16(s, g) \
    asm volatile("cp.async.cg.shared.global [%0], [%1], 16;" :: "r"(s), "l"(g))
#define CP_COMMIT() asm volatile("cp.async.commit_group;" ::: "memory")
#define CP_WAIT0()  asm volatile("cp.async.wait_group 0;" ::: "memory")
#define CP_WAIT1()  asm volatile("cp.async.wait_group 1;" ::: "memory")

// ---------------- weight conversion ----------------
__global__ void __launch_bounds__(256)
cvt_w2(const float* __restrict__ s0, __half* __restrict__ d0, int n0,
       const float* __restrict__ s1, __half* __restrict__ d1, int n1)
{
    int i = blockIdx.x * 256 + threadIdx.x;
    const float* s; __half* d;
    if (i < n0) { s = s0; d = d0; }
    else { i -= n0; if (i >= n1) return; s = s1; d = d1; }
    float4 v = ((const float4*)s)[i];
    ((__half2*)d)[i*2]   = __floats2half2_rn(v.x, v.y);
    ((__half2*)d)[i*2+1] = __floats2half2_rn(v.z, v.w);
}

// ---------------- LayerNorm -> fp16 hi/lo ----------------
__global__ void __launch_bounds__(256)
ln_f16(const float* __restrict__ x, const float* __restrict__ w,
       const float* __restrict__ b, __half* __restrict__ yh, __half* __restrict__ yl)
{
    __shared__ float red[16];
    int row = blockIdx.x, t = threadIdx.x;
    float4 v = ((const float4*)(x + (size_t)row * 1024))[t];
    float s  = v.x + v.y + v.z + v.w;
    float ss = v.x*v.x + v.y*v.y + v.z*v.z + v.w*v.w;
    #pragma unroll
    for (int o = 16; o; o >>= 1) {
        s  += __shfl_xor_sync(~0u, s, o);
        ss += __shfl_xor_sync(~0u, ss, o);
    }
    if ((t & 31) == 0) { red[t>>5] = s; red[(t>>5)+8] = ss; }
    __syncthreads();
    if (t == 0) {
        float ts=0.f, tss=0.f;
        #pragma unroll
        for (int i = 0; i < 8; ++i) { ts += red[i]; tss += red[i+8]; }
        float mu = ts * (1.f/1024.f);
        red[0] = mu; red[1] = rsqrtf(tss*(1.f/1024.f) - mu*mu + 1e-5f);
    }
    __syncthreads();
    float mu = red[0], rs = red[1];
    float4 wv = ((const float4*)w)[t];
    float4 bv = ((const float4*)b)[t];
    float o0 = (v.x-mu)*rs*wv.x + bv.x, o1 = (v.y-mu)*rs*wv.y + bv.y;
    float o2 = (v.z-mu)*rs*wv.z + bv.z, o3 = (v.w-mu)*rs*wv.w + bv.w;
    __half h0,h1,h2,h3,l0,l1,l2,l3;
    h16split(o0,h0,l0); h16split(o1,h1,l1); h16split(o2,h2,l2); h16split(o3,h3,l3);
    size_t oi = ((size_t)row*1024 + t*4) >> 1;
    __half2 pa, pb;
    pa.x=h0;pa.y=h1;pb.x=h2;pb.y=h3; ((__half2*)yh)[oi]=pa; ((__half2*)yh)[oi+1]=pb;
    pa.x=l0;pa.y=l1;pb.x=l2;pb.y=l3; ((__half2*)yl)[oi]=pa; ((__half2*)yl)[oi+1]=pb;
}

// ---- fp16x2 GEMM: A split (hi/lo), B single; 3-stage, 2 CTAs/SM ----
#define ATILE_B  10240
#define STAGE_H  30720
#define GSMEM_H  (3*STAGE_H)

__device__ __forceinline__ void issue_stage_h(
    const __half* __restrict__ Ah, const __half* __restrict__ Al,
    const __half* __restrict__ Bs,
    uint32_t sbase, int bm, int bn, int ko, int K, int tid)
{
    #pragma unroll
    for (int i = 0; i < 6; ++i) {
        int lin = tid + (i << 8);
        int tile = lin >> 9;
        int wit = lin & 511;
        int r = wit >> 2, ch = wit & 3;
        const __half* gp;
        if      (tile == 0) gp = Ah + (size_t)(bm + r) * K + ko + ch*8;
        else if (tile == 1) gp = Al + (size_t)(bm + r) * K + ko + ch*8;
        else                gp = Bs + (size_t)(bn + r) * K + ko + ch*8;
        CP_ASYNC16(sbase + tile*ATILE_B + r*80 + ch*16, gp);
    }
    CP_COMMIT();
}

// EPI 0: QKV scatter(+bias) | 1: +bias+res->outf | 2: split(relu·mask) | 3: res+acc·mask
template<int EPI>
__global__ void __launch_bounds__(256, 2)
tc_gemm16(const __half* __restrict__ Ah, const __half* __restrict__ Al,
          const __half* __restrict__ Bs,
          const float* __restrict__ bias, const float* __restrict__ aux,
          const float* __restrict__ res, float* __restrict__ outf,
          __half* __restrict__ outh, __half* __restrict__ outl, int N, int K)
{
    extern __shared__ char smem[];
    uint32_t sb = s2u(smem);
    const int tid = threadIdx.x, lane = tid & 31, wid = tid >> 5;
    const int wm = wid & 3, wn = wid >> 2;
    const int bm = blockIdx.y << 7, bn = blockIdx.x << 7;

    float acc[2][8][4];
    #pragma unroll
    for (int i = 0; i < 2; ++i)
        #pragma unroll
        for (int j = 0; j < 8; ++j)
            #pragma unroll
            for (int q = 0; q < 4; ++q) acc[i][j][q] = 0.f;

    const int ktn = K >> 5;
    issue_stage_h(Ah, Al, Bs, sb, bm, bn, 0, K, tid);
    if (ktn > 1) issue_stage_h(Ah, Al, Bs, sb + STAGE_H, bm, bn, 32, K, tid);

    const int a_ro = (lane & 15);
    const int a_ko = (lane >> 4) * 8;
    const int b_rp = ((lane >> 4) & 1) * 8 + (lane & 7);
    const int b_ko = ((lane >> 3) & 1) * 8;

    for (int kt = 0; kt < ktn; ++kt) {
        if (kt + 1 < ktn) CP_WAIT1(); else CP_WAIT0();
        __syncthreads();
        if (kt + 2 < ktn)
            issue_stage_h(Ah, Al, Bs, sb + ((kt + 2) % 3) * STAGE_H,
                          bm, bn, (kt + 2) * 32, K, tid);
        uint32_t st = sb + (kt % 3) * STAGE_H;
        #pragma unroll
        for (int ks = 0; ks < 2; ++ks) {
            uint32_t ahi[2][4], alo[2][4], bfr[4][4];
            #pragma unroll
            for (int mf = 0; mf < 2; ++mf) {
                uint32_t ad = st + (wm*32 + mf*16 + a_ro)*80 + (ks*16 + a_ko)*2;
                ldsm4(ahi[mf], ad);
                ldsm4(alo[mf], ad + ATILE_B);
            }
            #pragma unroll
            for (int np = 0; np < 4; ++np)
                ldsm4(bfr[np], st + 2*ATILE_B + (wn*64 + np*16 + b_rp)*80 + (ks*16 + b_ko)*2);
            #pragma unroll
            for (int np = 0; np < 4; ++np)
                #pragma unroll
                for (int mf = 0; mf < 2; ++mf) {
                    mma16816h(acc[mf][np*2  ], ahi[mf], &bfr[np][0]);
                    mma16816h(acc[mf][np*2+1], ahi[mf], &bfr[np][2]);
                }
            #pragma unroll
            for (int np = 0; np < 4; ++np)
                #pragma unroll
                for (int mf = 0; mf < 2; ++mf) {
                    mma16816h(acc[mf][np*2  ], alo[mf], &bfr[np][0]);
                    mma16816h(acc[mf][np*2+1], alo[mf], &bfr[np][2]);
                }
        }
    }

    const int tr = lane >> 2;
    const int tc = (lane & 3) * 2;
    #pragma unroll
    for (int mf = 0; mf < 2; ++mf) {
        #pragma unroll
        for (int nf = 0; nf < 8; ++nf) {
            int gj = bn + wn*64 + nf*8 + tc;
            float2 b2 = *(const float2*)&bias[gj];
            #pragma unroll
            for (int h = 0; h < 2; ++h) {
                int gi = bm + wm*32 + mf*16 + tr + h*8;
                float v0 = acc[mf][nf][h*2]   + b2.x;
                float v1 = acc[mf][nf][h*2+1] + b2.y;
                size_t off = (size_t)gi * N + gj;
                if (EPI == 0) {
                    int wh = gj >> 10, hh = (gj >> 6) & 15, d = gj & 63;
                    int bb = gi >> 10, nn = gi & 1023;
                    size_t idx = (((size_t)(bb*16 + hh))*1024 + nn)*64 + d;
                    if (wh == 0) {
                        __half h0,l0,h1,l1;
                        h16split(v0,h0,l0); h16split(v1,h1,l1);
                        __half2 ph, pl; ph.x=h0; ph.y=h1; pl.x=l0; pl.y=l1;
                        *(__half2*)&g_qh[idx] = ph; *(__half2*)&g_ql[idx] = pl;
                    } else if (wh == 1) {
                        *(__half2*)&g_k16[idx] = __floats2half2_rn(v0, v1);
                    } else {
                        *(__half2*)&g_v[idx] = __floats2half2_rn(v0, v1);
                    }
                } else if (EPI == 1) {
                    float2 rr = *(const float2*)&res[off];
                    float2 o; o.x = v0 + rr.x; o.y = v1 + rr.y;
                    *(float2*)&outf[off] = o;
                } else if (EPI == 2) {
                    float2 m = *(const float2*)&aux[off];
                    v0 = (m.x > 0.5f) ? fmaxf(v0, 0.f) : 0.f;
                    v1 = (m.y > 0.5f) ? fmaxf(v1, 0.f) : 0.f;
                    __half h0,l0,h1,l1;
                    h16split(v0,h0,l0); h16split(v1,h1,l1);
                    __half2 p; p.x=h0; p.y=h1; *(__half2*)&outh[off] = p;
                    p.x=l0; p.y=l1;            *(__half2*)&outl[off] = p;
                } else {
                    float2 m  = *(const float2*)&aux[off];
                    float2 rr = *(const float2*)&res[off];
                    float2 o;
                    o.x = rr.x + ((m.x > 0.5f) ? v0 : 0.f);
                    o.y = rr.y + ((m.y > 0.5f) ? v1 : 0.f);
                    *(float2*)&outf[off] = o;
                }
            }
        }
    }
}

// ------- sparse attention: fp16 scores, seeded search, scan compaction ----
#define SS_STR  1034
#define SS_OFF  11520
#define ATTN_SMEM (9216 + 36864 + 32*SS_STR*4)

__device__ __forceinline__ void issue_k(uint32_t sb, size_t bhoff, int kt, int buf, int tid) {
    #pragma unroll
    for (int i = 0; i < 2; ++i) {
        int lin = tid + (i << 9);
        int r = lin >> 3, ch = lin & 7;
        const __half* gsrc = g_k16 + bhoff + (size_t)(kt*128 + r)*64 + ch*8;
        CP_ASYNC16(sb + 9216 + buf*18432 + r*144 + ch*16, gsrc);
    }
    CP_COMMIT();
}

__device__ __forceinline__ float dec(unsigned ub) {
    unsigned fb = ub ^ ((ub & 0x80000000u) ? 0x80000000u : 0xFFFFFFFFu);
    return __uint_as_float(fb);
}

__global__ void __launch_bounds__(512)
attn_kernel()
{
    extern __shared__ char smraw[];
    float* smf = (float*)smraw;
    uint32_t sb = s2u(smraw);

    int blk = blockIdx.x, bh = blk >> 5, n0 = (blk & 31) << 5;
    int tid = threadIdx.x, lane = tid & 31, w = tid >> 5;
    const size_t bhoff = (size_t)bh * 65536;

    {
        int tile = tid >> 8, wit = tid & 255, r = wit >> 3, ch = wit & 7;
        const __half* gsrc = (tile ? g_ql : g_qh) + bhoff + (size_t)(n0 + r)*64 + ch*8;
        *(uint4*)(smraw + tile*4608 + r*144 + ch*16) = *(const uint4*)gsrc;
    }
    issue_k(sb, bhoff, 0, 0, tid);
    __syncthreads();

    const int wm = w & 1, wn = w >> 1;
    const int a_ro = lane & 15, a_ko = (lane >> 4) * 8;
    const int b_rp = ((lane >> 4) & 1) * 8 + (lane & 7);
    const int b_ko = ((lane >> 3) & 1) * 8;
    uint32_t qhi[4][4], qlo[4][4];
    #pragma unroll
    for (int ks = 0; ks < 4; ++ks) {
        uint32_t qa = sb + (wm*16 + a_ro)*144 + (ks*16 + a_ko)*2;
        ldsm4(qhi[ks], qa);
        ldsm4(qlo[ks], qa + 4608);
    }
    const int tr = lane >> 2, tc = (lane & 3) * 2;

    // ---- phase 1: scores via fp16 HMMA (double-buffered K) ----
    for (int kt = 0; kt < 8; ++kt) {
        CP_WAIT0();
        __syncthreads();
        if (kt < 7) issue_k(sb, bhoff, kt + 1, (kt + 1) & 1, tid);
        uint32_t kb = sb + 9216 + (kt & 1)*18432;
        float acc[2][4];
        #pragma unroll
        for (int nf = 0; nf < 2; ++nf)
            #pragma unroll
            for (int q = 0; q < 4; ++q) acc[nf][q] = 0.f;
        #pragma unroll
        for (int ks = 0; ks < 4; ++ks) {
            uint32_t bd = kb + (wn*16 + b_rp)*144 + (ks*16 + b_ko)*2;
            uint32_t bfr[4];
            ldsm4(bfr, bd);
            mma16816h(acc[0], qhi[ks], &bfr[0]);
            mma16816h(acc[1], qhi[ks], &bfr[2]);
            mma16816h(acc[0], qlo[ks], &bfr[0]);
            mma16816h(acc[1], qlo[ks], &bfr[2]);
        }
        #pragma unroll
        for (int nf = 0; nf < 2; ++nf) {
            int key = kt*128 + wn*16 + nf*8 + tc;
            int row0 = wm*16 + tr;
            float2 o;
            o.x = acc[nf][0]*0.125f; o.y = acc[nf][1]*0.125f;
            *(float2*)&smf[SS_OFF + row0*SS_STR + key] = o;
            o.x = acc[nf][2]*0.125f; o.y = acc[nf][3]*0.125f;
            *(float2*)&smf[SS_OFF + (row0+8)*SS_STR + key] = o;
        }
    }
    __syncthreads();

    // ---- per-row: seeded early-exit top-k, scan compaction, PV ----
    int r0 = 2 * w;
    float o00=0, o01=0, o10=0, o11=0;
    const __half* Vb = g_v + bhoff;
    #pragma unroll 1
    for (int rr = 0; rr < 2; ++rr) {
        float* srow = &smf[SS_OFF + (r0 + rr) * SS_STR];
        unsigned key[32];
        unsigned kmax = 0u, kmin = 0xFFFFFFFFu;
        #pragma unroll
        for (int i = 0; i < 32; ++i) {
            float s = srow[lane + 32*i];
            unsigned ub = __float_as_uint(s);
            unsigned k = ub ^ (((unsigned)((int)ub >> 31)) | 0x80000000u);
            key[i] = k;
            kmax = k > kmax ? k : kmax;
            kmin = k < kmin ? k : kmin;
        }
        kmax = __reduce_max_sync(~0u, kmax);
        kmin = __reduce_min_sync(~0u, kmin);
        float lmax = dec(kmax);

        // binary search seeded with true data range
        unsigned T;
        {
            unsigned lo = kmin, hi = kmax;
            while (lo < hi) {
                unsigned mid = lo + (unsigned)(((unsigned long long)(hi - lo) + 1ull) >> 1);
                unsigned c = 0;
                #pragma unroll
                for (int i = 0; i < 32; ++i) c += (key[i] >= mid) ? 1u : 0u;
                c = __reduce_add_sync(~0u, c);
                if (c == (unsigned)KSP) { lo = mid; break; }
                if (c > (unsigned)KSP) lo = mid; else hi = mid - 1u;
            }
            T = lo;
        }

        unsigned selmask = 0u;
        #pragma unroll
        for (int i = 0; i < 32; ++i)
            if (key[i] >= T) selmask |= (1u << i);
        int c = __popc(selmask);

        int off = c;
        #pragma unroll
        for (int o = 1; o < 32; o <<= 1) {
            int nsh = __shfl_up_sync(~0u, off, o);
            if (lane >= o) off += nsh;
        }
        int total = __shfl_sync(~0u, off, 31);
        off -= c;
        int cnt = total > 128 ? 128 : total;

        uint2* lst = (uint2*)srow;
        float lsum = 0.f;
        unsigned m = selmask;
        while (m) {
            int i = __ffs(m) - 1;
            m &= m - 1u;
            float e = __expf(dec(key[i]) - lmax);
            lsum += e;
            if (off < 128) {
                uint2 en; en.x = __float_as_uint(e); en.y = (unsigned)(lane + 32*i);
                lst[off] = en;
            }
            ++off;
        }
        #pragma unroll
        for (int o = 16; o; o >>= 1) lsum += __shfl_xor_sync(~0u, lsum, o);
        float inv = 1.f / lsum;
        __syncwarp();

        float a0 = 0.f, a1 = 0.f;
        #pragma unroll 8
        for (int j = 0; j < cnt; ++j) {
            uint2 e = lst[j];
            float p = __uint_as_float(e.x);
            __half2 hv = __ldg((const __half2*)(Vb + (size_t)e.y * 64) + lane);
            float2 v = __half22float2(hv);
            a0 = fmaf(p, v.x, a0);
            a1 = fmaf(p, v.y, a1);
        }
        a0 *= inv;
        a1 *= inv;
        if (rr == 0) { o00 = a0; o01 = a1; } else { o10 = a0; o11 = a1; }
    }

    int bb = bh >> 4, hh = bh & 15;
    {
        size_t base0 = ((size_t)(bb*1024 + n0 + r0    )) * 1024 + hh*64 + lane*2;
        size_t base1 = ((size_t)(bb*1024 + n0 + r0 + 1)) * 1024 + hh*64 + lane*2;
        __half h0, l0, h1, l1;
        h16split(o00, h0, l0); h16split(o01, h1, l1);
        __half2 ph, pl; ph.x = h0; ph.y = h1; pl.x = l0; pl.y = l1;
        *(__half2*)&g_ath[base0] = ph; *(__half2*)&g_atl[base0] = pl;
        h16split(o10, h0, l0); h16split(o11, h1, l1);
        ph.x = h0; ph.y = h1; pl.x = l0; pl.y = l1;
        *(__half2*)&g_ath[base1] = ph; *(__half2*)&g_atl[base1] = pl;
    }
}

// ---------------- launch ----------------
extern "C" void kernel_launch(void* const* d_in, const int* in_sizes, int n_in,
                              void* d_out, int out_size)
{
    (void)in_sizes; (void)n_in; (void)out_size;
    const float* x     = (const float*)d_in[0];
    const float* ln1_w = (const float*)d_in[1];
    const float* ln1_b = (const float*)d_in[2];
    const float* qkv_w = (const float*)d_in[3];
    const float* qkv_b = (const float*)d_in[4];
    const float* out_w = (const float*)d_in[5];
    const float* out_b = (const float*)d_in[6];
    const float* ln2_w = (const float*)d_in[7];
    const float* ln2_b = (const float*)d_in[8];
    const float* w1    = (const float*)d_in[9];
    const float* b1    = (const float*)d_in[10];
    const float* w2    = (const float*)d_in[11];
    const float* b2    = (const float*)d_in[12];
    const float* mask1 = (const float*)d_in[13];
    const float* mask2 = (const float*)d_in[14];
    float* out = (float*)d_out;

    void *x1, *xnh, *xnl, *hnh, *hnl, *ath, *atl, *h1h, *h1l,
         *qw16, *ow16, *w116, *w216;
    cudaGetSymbolAddress(&x1, g_x1);
    cudaGetSymbolAddress(&xnh, g_xnh); cudaGetSymbolAddress(&xnl, g_xnl);
    cudaGetSymbolAddress(&hnh, g_hnh); cudaGetSymbolAddress(&hnl, g_hnl);
    cudaGetSymbolAddress(&ath, g_ath); cudaGetSymbolAddress(&atl, g_atl);
    cudaGetSymbolAddress(&h1h, g_h1h); cudaGetSymbolAddress(&h1l, g_h1l);
    cudaGetSymbolAddress(&qw16, g_qw16);
    cudaGetSymbolAddress(&ow16, g_ow16);
    cudaGetSymbolAddress(&w116, g_w116);
    cudaGetSymbolAddress(&w216, g_w216);

    cudaFuncSetAttribute(attn_kernel, cudaFuncAttributeMaxDynamicSharedMemorySize, ATTN_SMEM);
    cudaFuncSetAttribute(tc_gemm16<0>, cudaFuncAttributeMaxDynamicSharedMemorySize, GSMEM_H);
    cudaFuncSetAttribute(tc_gemm16<1>, cudaFuncAttributeMaxDynamicSharedMemorySize, GSMEM_H);
    cudaFuncSetAttribute(tc_gemm16<2>, cudaFuncAttributeMaxDynamicSharedMemorySize, GSMEM_H);
    cudaFuncSetAttribute(tc_gemm16<3>, cudaFuncAttributeMaxDynamicSharedMemorySize, GSMEM_H);

    // order: [0]cvt [1]cvt [2]ln1 [3]gemm0  -> ncu captures fp16 gemm0
    cvt_w2<<<4096, 256>>>(qkv_w, (__half*)qw16, 786432,
                          out_w, (__half*)ow16, 262144);
    cvt_w2<<<8192, 256>>>(w1, (__half*)w116, 1048576,
                          w2, (__half*)w216, 1048576);

    ln_f16<<<M_, 256>>>(x, ln1_w, ln1_b, (__half*)xnh, (__half*)xnl);

    tc_gemm16<0><<<dim3(24, 64), 256, GSMEM_H>>>((__half*)xnh, (__half*)xnl,
        (__half*)qw16, qkv_b, nullptr, nullptr, nullptr, nullptr, nullptr, 3*C_, C_);

    attn_kernel<<<BH_*(N_/32), 512, ATTN_SMEM>>>();

    tc_gemm16<1><<<dim3(8, 64), 256, GSMEM_H>>>((__half*)ath, (__half*)atl,
        (__half*)ow16, out_b, nullptr, x, (float*)x1, nullptr, nullptr, C_, C_);

    ln_f16<<<M_, 256>>>((float*)x1, ln2_w, ln2_b, (__half*)hnh, (__half*)hnl);

    tc_gemm16<2><<<dim3(32, 64), 256, GSMEM_H>>>((__half*)hnh, (__half*)hnl,
        (__half*)w116, b1, mask1, nullptr, nullptr, (__half*)h1h, (__half*)h1l, FF_, C_);

    tc_gemm16<3><<<dim3(8, 64), 256, GSMEM_H>>>((__half*)h1h, (__half*)h1l,
        (__half*)w216, b2, mask2, (float*)x1, out, nullptr, nullptr, C_, FF_);
}